// round 1
// baseline (speedup 1.0000x reference)
#include <cuda_runtime.h>
#include <cstdint>

// Problem constants
#define BATCH 256
#define DIM   512
#define TT    96
#define NTOK  (BATCH * TT)        // 24576
#define KEMB  8192
#define NELEM (BATCH * DIM * TT)  // 12582912
#define KSPLIT 4
#define KCHUNK (KEMB / KSPLIT)    // 2048

// Scratch (static device allocations are allowed)
__device__ float g_xT[(size_t)NTOK * DIM];         // [N, D] contiguous tokens, 48 MB
__device__ float g_esq[KEMB];                      // ||e_k||^2
__device__ unsigned long long g_best[NTOK];        // packed (ordered_dist<<32)|idx
__device__ double g_loss_acc;

// ---------------------------------------------------------------------------
__global__ void k_init() {
    int i = blockIdx.x * blockDim.x + threadIdx.x;
    if (i < NTOK) g_best[i] = 0xFFFFFFFFFFFFFFFFULL;
    if (i == 0) g_loss_acc = 0.0;
}

// x [B, D, T] -> g_xT [(b*T+t), d]   (tiled 32x32 transpose per batch)
__global__ void k_transpose(const float* __restrict__ x) {
    __shared__ float tile[32][33];
    int b  = blockIdx.z;
    int d0 = blockIdx.y * 32;
    int t0 = blockIdx.x * 32;
    int tx = threadIdx.x, ty = threadIdx.y;
#pragma unroll
    for (int j = 0; j < 4; j++) {
        int d = d0 + ty + j * 8;
        tile[ty + j * 8][tx] = x[((size_t)b * DIM + d) * TT + t0 + tx];
    }
    __syncthreads();
#pragma unroll
    for (int j = 0; j < 4; j++) {
        int t = t0 + ty + j * 8;
        g_xT[((size_t)b * TT + t) * DIM + d0 + tx] = tile[tx][ty + j * 8];
    }
}

// ||e_k||^2 : one warp per embedding row
__global__ void k_esq(const float* __restrict__ E) {
    int warp = (blockIdx.x * blockDim.x + threadIdx.x) >> 5;
    int lane = threadIdx.x & 31;
    if (warp >= KEMB) return;
    const float4* row = reinterpret_cast<const float4*>(E + (size_t)warp * DIM);
    float s = 0.f;
#pragma unroll
    for (int i = 0; i < 4; i++) {
        float4 v = row[lane + i * 32];
        s += v.x * v.x + v.y * v.y + v.z * v.z + v.w * v.w;
    }
#pragma unroll
    for (int o = 16; o; o >>= 1) s += __shfl_xor_sync(~0u, s, o);
    if (lane == 0) g_esq[warp] = s;
}

// Fused distance-GEMM + argmin.
// Block: 128 token rows x 2048-embedding chunk. C tile 128x128, BK=16, 8x8/thread.
__global__ __launch_bounds__(256, 2) void k_gemm_argmin(const float* __restrict__ E) {
    __shared__ float As[16][128];
    __shared__ float Bs[16][128];
    __shared__ unsigned long long sbest[128];

    const int tid = threadIdx.x;
    const int tx = tid & 15, ty = tid >> 4;
    const int rowTile = blockIdx.x % (NTOK / 128);
    const int kchunk  = blockIdx.x / (NTOK / 128);
    const int row0 = rowTile * 128;
    const int k0   = kchunk * KCHUNK;

    for (int i = tid; i < 128; i += 256) sbest[i] = 0xFFFFFFFFFFFFFFFFULL;

    const int lr = tid >> 2;        // 0..63
    const int lc = (tid & 3) * 4;   // 0,4,8,12

    for (int kt = 0; kt < KCHUNK; kt += 128) {
        float acc[8][8];
#pragma unroll
        for (int i = 0; i < 8; i++)
#pragma unroll
            for (int j = 0; j < 8; j++) acc[i][j] = 0.f;

        for (int d0 = 0; d0 < DIM; d0 += 16) {
            __syncthreads();
#pragma unroll
            for (int p = 0; p < 2; p++) {
                int r = p * 64 + lr;
                float4 va = *reinterpret_cast<const float4*>(
                    &g_xT[(size_t)(row0 + r) * DIM + d0 + lc]);
                As[lc + 0][r] = va.x; As[lc + 1][r] = va.y;
                As[lc + 2][r] = va.z; As[lc + 3][r] = va.w;
                float4 vb = *reinterpret_cast<const float4*>(
                    &E[(size_t)(k0 + kt + r) * DIM + d0 + lc]);
                Bs[lc + 0][r] = vb.x; Bs[lc + 1][r] = vb.y;
                Bs[lc + 2][r] = vb.z; Bs[lc + 3][r] = vb.w;
            }
            __syncthreads();
#pragma unroll
            for (int kk = 0; kk < 16; kk++) {
                float a[8], b[8];
                *reinterpret_cast<float4*>(a)     = *reinterpret_cast<const float4*>(&As[kk][ty * 8]);
                *reinterpret_cast<float4*>(a + 4) = *reinterpret_cast<const float4*>(&As[kk][ty * 8 + 4]);
                *reinterpret_cast<float4*>(b)     = *reinterpret_cast<const float4*>(&Bs[kk][tx * 8]);
                *reinterpret_cast<float4*>(b + 4) = *reinterpret_cast<const float4*>(&Bs[kk][tx * 8 + 4]);
#pragma unroll
                for (int i = 0; i < 8; i++)
#pragma unroll
                    for (int j = 0; j < 8; j++)
                        acc[i][j] = fmaf(a[i], b[j], acc[i][j]);
            }
        }

        // Epilogue: score = ||e||^2 - 2*dot ; per-row argmin (tie -> lowest idx)
#pragma unroll
        for (int i = 0; i < 8; i++) {
            int row = ty * 8 + i;
            float best = __int_as_float(0x7f800000);  // +inf
            int bidx = 0;
#pragma unroll
            for (int j = 0; j < 8; j++) {
                int k = k0 + kt + tx * 8 + j;
                float sc = g_esq[k] - 2.0f * acc[i][j];
                if (sc < best || (sc == best && k < bidx)) { best = sc; bidx = k; }
            }
#pragma unroll
            for (int o = 8; o; o >>= 1) {
                float ob = __shfl_xor_sync(~0u, best, o, 16);
                int   oi = __shfl_xor_sync(~0u, bidx, o, 16);
                if (ob < best || (ob == best && oi < bidx)) { best = ob; bidx = oi; }
            }
            if (tx == 0) {
                unsigned ub = __float_as_uint(best);
                ub = (ub & 0x80000000u) ? ~ub : (ub | 0x80000000u);  // order-preserving map
                unsigned long long packed =
                    ((unsigned long long)ub << 32) | (unsigned)bidx;
                if (packed < sbest[row]) sbest[row] = packed;  // single writer per row
            }
        }
    }
    __syncthreads();
    for (int i = tid; i < 128; i += 256)
        atomicMin(&g_best[row0 + i], sbest[i]);
}

// Gather quantized = E[idx] and permute back to [B, D, T] with coalesced writes.
__global__ void k_output(const float* __restrict__ E, float* __restrict__ out) {
    __shared__ float s[TT][68];   // pad 68 avoids bank conflicts, keeps 16B align
    __shared__ int sidx[TT];
    int b  = blockIdx.y;
    int d0 = blockIdx.x * 64;
    int tid = threadIdx.x;
    if (tid < TT) sidx[tid] = (int)(g_best[(size_t)b * TT + tid] & 0xFFFFFFFFu);
    __syncthreads();
    for (int i = tid; i < TT * 16; i += 256) {      // load 96 rows x 64 floats
        int t = i >> 4, c = (i & 15) * 4;
        float4 v = *reinterpret_cast<const float4*>(
            E + (size_t)sidx[t] * DIM + d0 + c);
        s[t][c] = v.x; s[t][c + 1] = v.y; s[t][c + 2] = v.z; s[t][c + 3] = v.w;
    }
    __syncthreads();
    for (int i = tid; i < 64 * TT; i += 256) {      // write contiguous along t
        int dd = i / TT, t = i % TT;
        out[((size_t)b * DIM + d0 + dd) * TT + t] = s[t][dd];
    }
}

// loss accumulation: one warp per token row
__global__ void k_loss(const float* __restrict__ E) {
    __shared__ float wsum[8];
    int warp = threadIdx.x >> 5, lane = threadIdx.x & 31;
    int n = blockIdx.x * 8 + warp;
    int idx = (int)(g_best[n] & 0xFFFFFFFFu);
    const float4* e4 = reinterpret_cast<const float4*>(E + (size_t)idx * DIM);
    const float4* x4 = reinterpret_cast<const float4*>(g_xT + (size_t)n * DIM);
    float s = 0.f;
#pragma unroll
    for (int i = 0; i < 4; i++) {
        float4 a = e4[lane + i * 32], b = x4[lane + i * 32];
        float dx = a.x - b.x, dy = a.y - b.y, dz = a.z - b.z, dw = a.w - b.w;
        s += dx * dx + dy * dy + dz * dz + dw * dw;
    }
#pragma unroll
    for (int o = 16; o; o >>= 1) s += __shfl_xor_sync(~0u, s, o);
    if (lane == 0) wsum[warp] = s;
    __syncthreads();
    if (threadIdx.x == 0) {
        float t = 0.f;
#pragma unroll
        for (int i = 0; i < 8; i++) t += wsum[i];
        atomicAdd(&g_loss_acc, (double)t);
    }
}

__global__ void k_finalize(float* out, int out_size) {
    if (out_size > NELEM)
        out[NELEM] = (float)(1.25 * g_loss_acc / (double)((size_t)NTOK * DIM));
}

// ---------------------------------------------------------------------------
extern "C" void kernel_launch(void* const* d_in, const int* in_sizes, int n_in,
                              void* d_out, int out_size) {
    const float* x = (const float*)d_in[0];
    const float* E = (const float*)d_in[1];
    float* out = (float*)d_out;

    k_init<<<(NTOK + 255) / 256, 256>>>();
    k_transpose<<<dim3(TT / 32, DIM / 32, BATCH), dim3(32, 8)>>>(x);
    k_esq<<<KEMB / 8, 256>>>(E);
    k_gemm_argmin<<<(NTOK / 128) * KSPLIT, 256>>>(E);
    k_output<<<dim3(DIM / 64, BATCH), 256>>>(E, out);
    k_loss<<<NTOK / 8, 256>>>(E);
    k_finalize<<<1, 1>>>(out, out_size);
}

// round 2
// speedup vs baseline: 2.2745x; 2.2745x over previous
#include <cuda_runtime.h>
#include <cuda_fp16.h>
#include <cstdint>

// Problem constants
#define BATCH 256
#define DIM   512
#define TT    96
#define NTOK  (BATCH * TT)        // 24576
#define KEMB  8192
#define NELEM (BATCH * DIM * TT)  // 12582912
#define KCAT  (3 * DIM)           // 1536 : [hi|hi|lo] x [hi|lo|hi]

// GEMM tiling
#define BM 128
#define BN 128
#define BK 32
#define NKIT (KCAT / BK)          // 48
#define LDS_PAD 40                // halfs per smem row (32 + 8 pad), 80B, 16B-aligned segs

// Scratch (static device allocations are allowed)
__device__ __half g_A[(size_t)NTOK * KCAT];    // 75.5 MB
__device__ __half g_B[(size_t)KEMB * KCAT];    // 25.2 MB
__device__ float  g_xT[(size_t)NTOK * DIM];    // 48 MB (fp32 tokens for loss)
__device__ float  g_esq[KEMB];
__device__ unsigned long long g_best[NTOK];
__device__ double g_loss_acc;

// ---------------------------------------------------------------------------
__global__ void k_init() {
    int i = blockIdx.x * blockDim.x + threadIdx.x;
    if (i < NTOK) g_best[i] = 0xFFFFFFFFFFFFFFFFULL;
    if (i == 0) g_loss_acc = 0.0;
}

// x [B, D, T] -> g_xT [(b*T+t), d] fp32  AND  g_A fp16 split [row][hi|hi|lo]
__global__ void k_prep_x(const float* __restrict__ x) {
    __shared__ float tile[32][33];
    int b  = blockIdx.z;
    int d0 = blockIdx.y * 32;
    int t0 = blockIdx.x * 32;
    int tx = threadIdx.x, ty = threadIdx.y;
#pragma unroll
    for (int j = 0; j < 4; j++) {
        int d = d0 + ty + j * 8;
        tile[ty + j * 8][tx] = x[((size_t)b * DIM + d) * TT + t0 + tx];
    }
    __syncthreads();
#pragma unroll
    for (int j = 0; j < 4; j++) {
        int t = t0 + ty + j * 8;
        size_t row = (size_t)b * TT + t;
        float v = tile[tx][ty + j * 8];
        g_xT[row * DIM + d0 + tx] = v;
        __half hi = __float2half(v);
        __half lo = __float2half(v - __half2float(hi));
        g_A[row * KCAT + (d0 + tx)]        = hi;
        g_A[row * KCAT + DIM + (d0 + tx)]  = hi;
        g_A[row * KCAT + 2 * DIM + (d0 + tx)] = lo;
    }
}

// E [K, D] -> g_B fp16 split [n][hi|lo|hi]
__global__ void k_prep_e(const float* __restrict__ E) {
    int i = blockIdx.x * blockDim.x + threadIdx.x;
    if (i >= KEMB * DIM) return;
    int n = i >> 9, d = i & 511;
    float v = E[i];
    __half hi = __float2half(v);
    __half lo = __float2half(v - __half2float(hi));
    size_t base = (size_t)n * KCAT;
    g_B[base + d]            = hi;
    g_B[base + DIM + d]      = lo;
    g_B[base + 2 * DIM + d]  = hi;
}

// ||e_k||^2 : one warp per embedding row (fp32 exact)
__global__ void k_esq(const float* __restrict__ E) {
    int warp = (blockIdx.x * blockDim.x + threadIdx.x) >> 5;
    int lane = threadIdx.x & 31;
    if (warp >= KEMB) return;
    const float4* row = reinterpret_cast<const float4*>(E + (size_t)warp * DIM);
    float s = 0.f;
#pragma unroll
    for (int i = 0; i < 4; i++) {
        float4 v = row[lane + i * 32];
        s += v.x * v.x + v.y * v.y + v.z * v.z + v.w * v.w;
    }
#pragma unroll
    for (int o = 16; o; o >>= 1) s += __shfl_xor_sync(~0u, s, o);
    if (lane == 0) g_esq[warp] = s;
}

// ---------------------------------------------------------------------------
__device__ __forceinline__ unsigned long long pack_score(float s, int idx) {
    unsigned u = __float_as_uint(s);
    u = (u & 0x80000000u) ? ~u : (u | 0x80000000u);  // order-preserving
    return ((unsigned long long)u << 32) | (unsigned)idx;
}

__device__ __forceinline__ void cp_async16(uint32_t smem, const void* gmem) {
    asm volatile("cp.async.ca.shared.global [%0], [%1], 16;\n" ::"r"(smem), "l"(gmem));
}

// Fused fp16-split distance GEMM + argmin using mma.sync (HMMA), fp32 accum.
// CTA = 128 rows x 128 embeddings, K = 1536. 8 warps, warp tile 64x32.
__global__ __launch_bounds__(256) void k_gemm_hmma() {
    __shared__ __half As[2][BM][LDS_PAD];
    __shared__ __half Bs[2][BN][LDS_PAD];
    __shared__ unsigned long long sbest[BM];

    const int tid  = threadIdx.x;
    const int lane = tid & 31;
    const int wid  = tid >> 5;
    const int warprow = wid >> 2;      // 0..1 -> m offset 0/64
    const int warpcol = wid & 3;       // 0..3 -> n offset 0/32/64/96
    const int row0 = blockIdx.y * BM;
    const int n0   = blockIdx.x * BN;

    for (int i = tid; i < BM; i += 256) sbest[i] = 0xFFFFFFFFFFFFFFFFULL;

    // global->smem mapping: each thread loads 2x16B for A and 2x16B for B
    const int ldrow = tid >> 1;                 // 0..127
    const int ldseg = (tid & 1) * 2;            // 0 or 2 (each seg = 8 halfs)
    const __half* gA = g_A + (size_t)(row0 + ldrow) * KCAT + ldseg * 8;
    const __half* gB = g_B + (size_t)(n0 + ldrow) * KCAT + ldseg * 8;
    uint32_t sA0 = (uint32_t)__cvta_generic_to_shared(&As[0][ldrow][ldseg * 8]);
    uint32_t sB0 = (uint32_t)__cvta_generic_to_shared(&Bs[0][ldrow][ldseg * 8]);
    const uint32_t stageBytesA = (uint32_t)(sizeof(__half) * BM * LDS_PAD);
    const uint32_t stageBytesB = (uint32_t)(sizeof(__half) * BN * LDS_PAD);

    auto load_stage = [&](int kt, int buf) {
        const __half* a = gA + (size_t)kt * BK;
        const __half* b = gB + (size_t)kt * BK;
        uint32_t sa = sA0 + buf * stageBytesA;
        uint32_t sb = sB0 + buf * stageBytesB;
        cp_async16(sa, a);
        cp_async16(sa + 16, a + 8);
        cp_async16(sb, b);
        cp_async16(sb + 16, b + 8);
    };

    float acc[16][4];
#pragma unroll
    for (int i = 0; i < 16; i++)
#pragma unroll
        for (int c = 0; c < 4; c++) acc[i][c] = 0.f;

    // ldmatrix source addresses (per-lane), as byte offsets into a stage
    // A: row = m0 + (lane&15), col = k0 + ((lane>>4)<<3)
    const int a_r = lane & 15;
    const int a_c = (lane >> 4) << 3;
    // B: row = n + (lane&7), col = k0 + ((lane&8) ? 8 : 0)
    const int b_r = lane & 7;
    const int b_c = (lane & 8);

    uint32_t sAbase = (uint32_t)__cvta_generic_to_shared(&As[0][0][0]);
    uint32_t sBbase = (uint32_t)__cvta_generic_to_shared(&Bs[0][0][0]);

    load_stage(0, 0);
    asm volatile("cp.async.commit_group;\n");

    for (int kt = 0; kt < NKIT; kt++) {
        int p = kt & 1;
        if (kt + 1 < NKIT) {
            load_stage(kt + 1, (kt + 1) & 1);
            asm volatile("cp.async.commit_group;\n");
            asm volatile("cp.async.wait_group 1;\n");
        } else {
            asm volatile("cp.async.wait_group 0;\n");
        }
        __syncthreads();

#pragma unroll
        for (int kk = 0; kk < 2; kk++) {   // two k16 steps per BK=32
            int k0 = kk * 16;
            uint32_t a_reg[4][4];
            uint32_t b_reg[4][2];
#pragma unroll
            for (int mf = 0; mf < 4; mf++) {
                int m0 = warprow * 64 + mf * 16;
                uint32_t addr = sAbase + p * stageBytesA +
                    (uint32_t)(((m0 + a_r) * LDS_PAD + k0 + a_c) * sizeof(__half));
                asm volatile(
                    "ldmatrix.sync.aligned.m8n8.x4.shared.b16 {%0,%1,%2,%3}, [%4];\n"
                    : "=r"(a_reg[mf][0]), "=r"(a_reg[mf][1]),
                      "=r"(a_reg[mf][2]), "=r"(a_reg[mf][3])
                    : "r"(addr));
            }
#pragma unroll
            for (int nf = 0; nf < 4; nf++) {
                int nn = warpcol * 32 + nf * 8;
                uint32_t addr = sBbase + p * stageBytesB +
                    (uint32_t)(((nn + b_r) * LDS_PAD + k0 + b_c) * sizeof(__half));
                asm volatile(
                    "ldmatrix.sync.aligned.m8n8.x2.shared.b16 {%0,%1}, [%2];\n"
                    : "=r"(b_reg[nf][0]), "=r"(b_reg[nf][1])
                    : "r"(addr));
            }
#pragma unroll
            for (int mf = 0; mf < 4; mf++)
#pragma unroll
                for (int nf = 0; nf < 4; nf++) {
                    asm volatile(
                        "mma.sync.aligned.m16n8k16.row.col.f32.f16.f16.f32 "
                        "{%0,%1,%2,%3}, {%4,%5,%6,%7}, {%8,%9}, {%0,%1,%2,%3};\n"
                        : "+f"(acc[mf * 4 + nf][0]), "+f"(acc[mf * 4 + nf][1]),
                          "+f"(acc[mf * 4 + nf][2]), "+f"(acc[mf * 4 + nf][3])
                        : "r"(a_reg[mf][0]), "r"(a_reg[mf][1]),
                          "r"(a_reg[mf][2]), "r"(a_reg[mf][3]),
                          "r"(b_reg[nf][0]), "r"(b_reg[nf][1]));
                }
        }
        __syncthreads();
    }

    // Epilogue: score = ||e||^2 - 2*dot ; per-row argmin with lowest-idx ties.
    // Thread owns: rows warprow*64 + mf*16 + (lane>>2) (+8), cols nf*8 + 2*(lane&3) (+1)
#pragma unroll
    for (int mf = 0; mf < 4; mf++) {
        int r0 = warprow * 64 + mf * 16 + (lane >> 2);
        unsigned long long best0 = 0xFFFFFFFFFFFFFFFFULL;
        unsigned long long best1 = 0xFFFFFFFFFFFFFFFFULL;
#pragma unroll
        for (int nf = 0; nf < 4; nf++) {
            int k = n0 + warpcol * 32 + nf * 8 + 2 * (lane & 3);
            float e0 = g_esq[k], e1 = g_esq[k + 1];
            unsigned long long c;
            c = pack_score(e0 - 2.f * acc[mf * 4 + nf][0], k);     if (c < best0) best0 = c;
            c = pack_score(e1 - 2.f * acc[mf * 4 + nf][1], k + 1); if (c < best0) best0 = c;
            c = pack_score(e0 - 2.f * acc[mf * 4 + nf][2], k);     if (c < best1) best1 = c;
            c = pack_score(e1 - 2.f * acc[mf * 4 + nf][3], k + 1); if (c < best1) best1 = c;
        }
#pragma unroll
        for (int o = 1; o < 4; o <<= 1) {
            unsigned long long t0 = __shfl_xor_sync(0xffffffffu, best0, o);
            unsigned long long t1 = __shfl_xor_sync(0xffffffffu, best1, o);
            if (t0 < best0) best0 = t0;
            if (t1 < best1) best1 = t1;
        }
        if ((lane & 3) == 0) {
            atomicMin(&sbest[r0], best0);
            atomicMin(&sbest[r0 + 8], best1);
        }
    }
    __syncthreads();
    for (int i = tid; i < BM; i += 256)
        atomicMin(&g_best[row0 + i], sbest[i]);
}

// ---------------------------------------------------------------------------
// Gather quantized = E[idx] and permute back to [B, D, T] with coalesced writes.
__global__ void k_output(const float* __restrict__ E, float* __restrict__ out) {
    __shared__ float s[TT][68];
    __shared__ int sidx[TT];
    int b  = blockIdx.y;
    int d0 = blockIdx.x * 64;
    int tid = threadIdx.x;
    if (tid < TT) sidx[tid] = (int)(g_best[(size_t)b * TT + tid] & 0xFFFFFFFFu);
    __syncthreads();
    for (int i = tid; i < TT * 16; i += 256) {
        int t = i >> 4, c = (i & 15) * 4;
        float4 v = *reinterpret_cast<const float4*>(
            E + (size_t)sidx[t] * DIM + d0 + c);
        s[t][c] = v.x; s[t][c + 1] = v.y; s[t][c + 2] = v.z; s[t][c + 3] = v.w;
    }
    __syncthreads();
    for (int i = tid; i < 64 * TT; i += 256) {
        int dd = i / TT, t = i % TT;
        out[((size_t)b * DIM + d0 + dd) * TT + t] = s[t][dd];
    }
}

// loss accumulation: one warp per token row
__global__ void k_loss(const float* __restrict__ E) {
    __shared__ float wsum[8];
    int warp = threadIdx.x >> 5, lane = threadIdx.x & 31;
    int n = blockIdx.x * 8 + warp;
    int idx = (int)(g_best[n] & 0xFFFFFFFFu);
    const float4* e4 = reinterpret_cast<const float4*>(E + (size_t)idx * DIM);
    const float4* x4 = reinterpret_cast<const float4*>(g_xT + (size_t)n * DIM);
    float s = 0.f;
#pragma unroll
    for (int i = 0; i < 4; i++) {
        float4 a = e4[lane + i * 32], b = x4[lane + i * 32];
        float dx = a.x - b.x, dy = a.y - b.y, dz = a.z - b.z, dw = a.w - b.w;
        s += dx * dx + dy * dy + dz * dz + dw * dw;
    }
#pragma unroll
    for (int o = 16; o; o >>= 1) s += __shfl_xor_sync(~0u, s, o);
    if (lane == 0) wsum[warp] = s;
    __syncthreads();
    if (threadIdx.x == 0) {
        float t = 0.f;
#pragma unroll
        for (int i = 0; i < 8; i++) t += wsum[i];
        atomicAdd(&g_loss_acc, (double)t);
    }
}

__global__ void k_finalize(float* out, int out_size) {
    if (out_size > NELEM)
        out[NELEM] = (float)(1.25 * g_loss_acc / (double)((size_t)NTOK * DIM));
}

// ---------------------------------------------------------------------------
extern "C" void kernel_launch(void* const* d_in, const int* in_sizes, int n_in,
                              void* d_out, int out_size) {
    const float* x = (const float*)d_in[0];
    const float* E = (const float*)d_in[1];
    float* out = (float*)d_out;

    k_init<<<(NTOK + 255) / 256, 256>>>();
    k_prep_x<<<dim3(TT / 32, DIM / 32, BATCH), dim3(32, 8)>>>(x);
    k_prep_e<<<(KEMB * DIM) / 256, 256>>>(E);
    k_esq<<<KEMB / 8, 256>>>(E);
    k_gemm_hmma<<<dim3(KEMB / BN, NTOK / BM), 256>>>();
    k_output<<<dim3(DIM / 64, BATCH), 256>>>(E, out);
    k_loss<<<NTOK / 8, 256>>>(E);
    k_finalize<<<1, 1>>>(out, out_size);
}

// round 4
// speedup vs baseline: 3.8291x; 1.6835x over previous
#include <cuda_runtime.h>
#include <cuda_fp16.h>
#include <cstdint>

// Problem constants
#define BATCH 256
#define DIM   512
#define TT    96
#define NTOK  (BATCH * TT)        // 24576
#define KEMB  8192
#define NELEM (BATCH * DIM * TT)  // 12582912

// GEMM tiling (K = DIM = 512, fp16 hi only)
#define BM 128
#define BN 128
#define BK 32
#define NKIT (DIM / BK)           // 16
#define LDS_PAD 40                // halfs per smem row (32 + 8 pad)

#define MARGIN_F 0.4f

// Scratch (static device allocations are allowed)
__device__ __half g_Ah[(size_t)NTOK * DIM];    // 25 MB fp16 hi tokens
__device__ __half g_Bh[(size_t)KEMB * DIM];    // 8.4 MB fp16 hi embeddings
__device__ float  g_xT[(size_t)NTOK * DIM];    // 48 MB fp32 tokens (loss + fallback)
__device__ float  g_esq[KEMB];
__device__ unsigned long long g_best[NTOK];    // packed (mapped_score<<32)|idx
__device__ unsigned int g_best2[NTOK];         // mapped second-best score
__device__ int g_nfall;
__device__ int g_fall[NTOK];
__device__ double g_loss_acc;

// ---------------------------------------------------------------------------
__device__ __forceinline__ unsigned long long pack_score(float s, int idx) {
    unsigned u = __float_as_uint(s);
    u = (u & 0x80000000u) ? ~u : (u | 0x80000000u);  // order-preserving map
    return ((unsigned long long)u << 32) | (unsigned)idx;
}
__device__ __forceinline__ float unmap_score(unsigned u) {
    unsigned v = (u & 0x80000000u) ? (u & 0x7FFFFFFFu) : ~u;
    return __uint_as_float(v);
}
__device__ __forceinline__ void cp_async16(uint32_t smem, const void* gmem) {
    asm volatile("cp.async.cg.shared.global [%0], [%1], 16;\n" ::"r"(smem), "l"(gmem));
}
__device__ __forceinline__ void upd2(unsigned long long& b1, unsigned& b2,
                                     unsigned long long c) {
    if (c < b1) { unsigned d = (unsigned)(b1 >> 32); if (d < b2) b2 = d; b1 = c; }
    else        { unsigned d = (unsigned)(c  >> 32); if (d < b2) b2 = d; }
}

// ---------------------------------------------------------------------------
__global__ void k_init() {
    int i = blockIdx.x * blockDim.x + threadIdx.x;
    if (i < NTOK) { g_best[i] = 0xFFFFFFFFFFFFFFFFULL; g_best2[i] = 0xFFFFFFFFu; }
    if (i == 0) { g_loss_acc = 0.0; g_nfall = 0; }
}

// x [B, D, T] -> g_xT fp32 [(b*T+t), d] AND g_Ah fp16 hi
__global__ void k_prep_x(const float* __restrict__ x) {
    __shared__ float tile[32][33];
    int b  = blockIdx.z;
    int d0 = blockIdx.y * 32;
    int t0 = blockIdx.x * 32;
    int tx = threadIdx.x, ty = threadIdx.y;
#pragma unroll
    for (int j = 0; j < 4; j++) {
        int d = d0 + ty + j * 8;
        tile[ty + j * 8][tx] = x[((size_t)b * DIM + d) * TT + t0 + tx];
    }
    __syncthreads();
#pragma unroll
    for (int j = 0; j < 4; j++) {
        int t = t0 + ty + j * 8;
        size_t row = (size_t)b * TT + t;
        float v = tile[tx][ty + j * 8];
        g_xT[row * DIM + d0 + tx] = v;
        g_Ah[row * DIM + d0 + tx] = __float2half(v);
    }
}

// E [K, D] -> g_Bh fp16 hi ; also per-row ||e||^2 via warp reduce done in k_esq
__global__ void k_prep_e(const float* __restrict__ E) {
    int i = blockIdx.x * blockDim.x + threadIdx.x;
    if (i >= KEMB * DIM) return;
    g_Bh[i] = __float2half(E[i]);
}

// ||e_k||^2 : one warp per embedding row (fp32 exact)
__global__ void k_esq(const float* __restrict__ E) {
    int warp = (blockIdx.x * blockDim.x + threadIdx.x) >> 5;
    int lane = threadIdx.x & 31;
    if (warp >= KEMB) return;
    const float4* row = reinterpret_cast<const float4*>(E + (size_t)warp * DIM);
    float s = 0.f;
#pragma unroll
    for (int i = 0; i < 4; i++) {
        float4 v = row[lane + i * 32];
        s += v.x * v.x + v.y * v.y + v.z * v.z + v.w * v.w;
    }
#pragma unroll
    for (int o = 16; o; o >>= 1) s += __shfl_xor_sync(~0u, s, o);
    if (lane == 0) g_esq[warp] = s;
}

// ---------------------------------------------------------------------------
// fp16-hi distance GEMM + fused per-row (min1, min2) tracking via HMMA.
// CTA = 128 rows x 128 embeddings, K = 512. 8 warps, warp tile 64x32.
__global__ __launch_bounds__(256) void k_gemm_hmma() {
    __shared__ __half As[2][BM][LDS_PAD];
    __shared__ __half Bs[2][BN][LDS_PAD];
    __shared__ unsigned long long sb1[BM];
    __shared__ unsigned int sb2[BM];

    const int tid  = threadIdx.x;
    const int lane = tid & 31;
    const int wid  = tid >> 5;
    const int warprow = wid >> 2;      // 0..1 -> m offset 0/64
    const int warpcol = wid & 3;       // 0..3 -> n offset 0/32/64/96
    const int row0 = blockIdx.y * BM;
    const int n0   = blockIdx.x * BN;

    for (int i = tid; i < BM; i += 256) {
        sb1[i] = 0xFFFFFFFFFFFFFFFFULL;
        sb2[i] = 0xFFFFFFFFu;
    }

    const int ldrow = tid >> 1;
    const int ldseg = (tid & 1) * 2;
    const __half* gA = g_Ah + (size_t)(row0 + ldrow) * DIM + ldseg * 8;
    const __half* gB = g_Bh + (size_t)(n0 + ldrow) * DIM + ldseg * 8;
    uint32_t sA0 = (uint32_t)__cvta_generic_to_shared(&As[0][ldrow][ldseg * 8]);
    uint32_t sB0 = (uint32_t)__cvta_generic_to_shared(&Bs[0][ldrow][ldseg * 8]);
    const uint32_t stageBytesA = (uint32_t)(sizeof(__half) * BM * LDS_PAD);
    const uint32_t stageBytesB = (uint32_t)(sizeof(__half) * BN * LDS_PAD);

    auto load_stage = [&](int kt, int buf) {
        const __half* a = gA + (size_t)kt * BK;
        const __half* b = gB + (size_t)kt * BK;
        uint32_t sa = sA0 + buf * stageBytesA;
        uint32_t sb = sB0 + buf * stageBytesB;
        cp_async16(sa, a);
        cp_async16(sa + 16, a + 8);
        cp_async16(sb, b);
        cp_async16(sb + 16, b + 8);
    };

    float acc[16][4];
#pragma unroll
    for (int i = 0; i < 16; i++)
#pragma unroll
        for (int c = 0; c < 4; c++) acc[i][c] = 0.f;

    const int a_r = lane & 15;
    const int a_c = (lane >> 4) << 3;
    const int b_r = lane & 7;
    const int b_c = (lane & 8);

    uint32_t sAbase = (uint32_t)__cvta_generic_to_shared(&As[0][0][0]);
    uint32_t sBbase = (uint32_t)__cvta_generic_to_shared(&Bs[0][0][0]);

    load_stage(0, 0);
    asm volatile("cp.async.commit_group;\n");

    for (int kt = 0; kt < NKIT; kt++) {
        int p = kt & 1;
        if (kt + 1 < NKIT) {
            load_stage(kt + 1, (kt + 1) & 1);
            asm volatile("cp.async.commit_group;\n");
            asm volatile("cp.async.wait_group 1;\n");
        } else {
            asm volatile("cp.async.wait_group 0;\n");
        }
        __syncthreads();

#pragma unroll
        for (int kk = 0; kk < 2; kk++) {
            int k0 = kk * 16;
            uint32_t a_reg[4][4];
            uint32_t b_reg[4][2];
#pragma unroll
            for (int mf = 0; mf < 4; mf++) {
                int m0 = warprow * 64 + mf * 16;
                uint32_t addr = sAbase + p * stageBytesA +
                    (uint32_t)(((m0 + a_r) * LDS_PAD + k0 + a_c) * sizeof(__half));
                asm volatile(
                    "ldmatrix.sync.aligned.m8n8.x4.shared.b16 {%0,%1,%2,%3}, [%4];\n"
                    : "=r"(a_reg[mf][0]), "=r"(a_reg[mf][1]),
                      "=r"(a_reg[mf][2]), "=r"(a_reg[mf][3])
                    : "r"(addr));
            }
#pragma unroll
            for (int nf = 0; nf < 4; nf++) {
                int nn = warpcol * 32 + nf * 8;
                uint32_t addr = sBbase + p * stageBytesB +
                    (uint32_t)(((nn + b_r) * LDS_PAD + k0 + b_c) * sizeof(__half));
                asm volatile(
                    "ldmatrix.sync.aligned.m8n8.x2.shared.b16 {%0,%1}, [%2];\n"
                    : "=r"(b_reg[nf][0]), "=r"(b_reg[nf][1])
                    : "r"(addr));
            }
#pragma unroll
            for (int mf = 0; mf < 4; mf++)
#pragma unroll
                for (int nf = 0; nf < 4; nf++) {
                    asm volatile(
                        "mma.sync.aligned.m16n8k16.row.col.f32.f16.f16.f32 "
                        "{%0,%1,%2,%3}, {%4,%5,%6,%7}, {%8,%9}, {%0,%1,%2,%3};\n"
                        : "+f"(acc[mf * 4 + nf][0]), "+f"(acc[mf * 4 + nf][1]),
                          "+f"(acc[mf * 4 + nf][2]), "+f"(acc[mf * 4 + nf][3])
                        : "r"(a_reg[mf][0]), "r"(a_reg[mf][1]),
                          "r"(a_reg[mf][2]), "r"(a_reg[mf][3]),
                          "r"(b_reg[nf][0]), "r"(b_reg[nf][1]));
                }
        }
        __syncthreads();
    }

    // Epilogue: score = ||e||^2 - 2*dot ; track per-row min1 (packed) + min2 (mapped).
#pragma unroll
    for (int mf = 0; mf < 4; mf++) {
        int r0 = warprow * 64 + mf * 16 + (lane >> 2);
        unsigned long long b1a = 0xFFFFFFFFFFFFFFFFULL, b1b = 0xFFFFFFFFFFFFFFFFULL;
        unsigned b2a = 0xFFFFFFFFu, b2b = 0xFFFFFFFFu;
#pragma unroll
        for (int nf = 0; nf < 4; nf++) {
            int k = n0 + warpcol * 32 + nf * 8 + 2 * (lane & 3);
            float e0 = g_esq[k], e1 = g_esq[k + 1];
            upd2(b1a, b2a, pack_score(e0 - 2.f * acc[mf * 4 + nf][0], k));
            upd2(b1a, b2a, pack_score(e1 - 2.f * acc[mf * 4 + nf][1], k + 1));
            upd2(b1b, b2b, pack_score(e0 - 2.f * acc[mf * 4 + nf][2], k));
            upd2(b1b, b2b, pack_score(e1 - 2.f * acc[mf * 4 + nf][3], k + 1));
        }
#pragma unroll
        for (int o = 1; o < 4; o <<= 1) {
            unsigned long long o1a = __shfl_xor_sync(0xffffffffu, b1a, o);
            unsigned long long o1b = __shfl_xor_sync(0xffffffffu, b1b, o);
            unsigned o2a = __shfl_xor_sync(0xffffffffu, b2a, o);
            unsigned o2b = __shfl_xor_sync(0xffffffffu, b2b, o);
            unsigned long long mxa = (b1a > o1a) ? b1a : o1a;
            unsigned long long mxb = (b1b > o1b) ? b1b : o1b;
            b1a = (b1a < o1a) ? b1a : o1a;
            b1b = (b1b < o1b) ? b1b : o1b;
            unsigned da = (unsigned)(mxa >> 32), db = (unsigned)(mxb >> 32);
            b2a = min(min(b2a, o2a), da);
            b2b = min(min(b2b, o2b), db);
        }
        if ((lane & 3) == 0) {
            unsigned long long old, disp;
            old = atomicMin(&sb1[r0], b1a);
            disp = (old > b1a) ? old : b1a;
            atomicMin(&sb2[r0], min(b2a, (unsigned)(disp >> 32)));
            old = atomicMin(&sb1[r0 + 8], b1b);
            disp = (old > b1b) ? old : b1b;
            atomicMin(&sb2[r0 + 8], min(b2b, (unsigned)(disp >> 32)));
        }
    }
    __syncthreads();
    for (int i = tid; i < BM; i += 256) {
        unsigned long long v1 = sb1[i];
        unsigned long long old = atomicMin(&g_best[row0 + i], v1);
        unsigned long long disp = (old > v1) ? old : v1;
        atomicMin(&g_best2[row0 + i], min(sb2[i], (unsigned)(disp >> 32)));
    }
}

// ---------------------------------------------------------------------------
// Flag rows with uncertain winner (approx gap < MARGIN) for exact rescore.
__global__ void k_select() {
    int i = blockIdx.x * blockDim.x + threadIdx.x;
    if (i >= NTOK) return;
    float s1 = unmap_score((unsigned)(g_best[i] >> 32));
    float s2 = unmap_score(g_best2[i]);
    if (s2 - s1 < MARGIN_F) {
        int p = atomicAdd(&g_nfall, 1);
        g_fall[p] = i;
        g_best[i] = 0xFFFFFFFFFFFFFFFFULL;
    }
}

// Exact fp32 rescore of flagged rows over all K embeddings.
// Grid = 512 CTAs: 64 batch slots x 8 embedding chunks of 1024.
__global__ __launch_bounds__(256) void k_fallback(const float* __restrict__ E) {
    __shared__ float xs[16][512];
    __shared__ int srow[16];
    __shared__ unsigned long long sb[16];
    const int n = g_nfall;
    const int chunk = blockIdx.x & 7;
    const int slot  = blockIdx.x >> 3;
    const int tid = threadIdx.x;

    for (int b = slot; b * 16 < n; b += 64) {
        int nr = min(16, n - b * 16);
        if (tid < 16) {
            srow[tid] = (tid < nr) ? g_fall[b * 16 + tid] : 0;
            sb[tid] = 0xFFFFFFFFFFFFFFFFULL;
        }
        __syncthreads();
        for (int idx = tid; idx < 16 * 512; idx += 256) {
            int r = idx >> 9, j = idx & 511;
            xs[r][j] = (r < nr) ? g_xT[(size_t)srow[r] * DIM + j] : 0.f;
        }
        __syncthreads();

        float bscore[16];
        int bidx[16];
#pragma unroll
        for (int r = 0; r < 16; r++) { bscore[r] = __int_as_float(0x7f800000); bidx[r] = 0; }

#pragma unroll 1
        for (int e = 0; e < 4; e++) {
            int k = chunk * 1024 + e * 256 + tid;
            float acc[16];
#pragma unroll
            for (int r = 0; r < 16; r++) acc[r] = 0.f;
            const float4* e4 = reinterpret_cast<const float4*>(E + (size_t)k * DIM);
            for (int jj = 0; jj < 128; jj++) {
                float4 v = e4[jj];
#pragma unroll
                for (int r = 0; r < 16; r++) {
                    float4 xv = *reinterpret_cast<const float4*>(&xs[r][jj * 4]);
                    acc[r] += v.x * xv.x + v.y * xv.y + v.z * xv.z + v.w * xv.w;
                }
            }
            float ek = g_esq[k];
#pragma unroll
            for (int r = 0; r < 16; r++) {
                float sc = ek - 2.f * acc[r];
                if (sc < bscore[r]) { bscore[r] = sc; bidx[r] = k; }
            }
        }
#pragma unroll
        for (int r = 0; r < 16; r++)
            if (r < nr) atomicMin(&sb[r], pack_score(bscore[r], bidx[r]));
        __syncthreads();
        if (tid < nr) atomicMin(&g_best[srow[tid]], sb[tid]);
        __syncthreads();
    }
}

// ---------------------------------------------------------------------------
// Gather quantized = E[idx] and permute back to [B, D, T] with coalesced writes.
__global__ void k_output(const float* __restrict__ E, float* __restrict__ out) {
    __shared__ float s[TT][68];
    __shared__ int sidx[TT];
    int b  = blockIdx.y;
    int d0 = blockIdx.x * 64;
    int tid = threadIdx.x;
    if (tid < TT) sidx[tid] = (int)(g_best[(size_t)b * TT + tid] & 0xFFFFFFFFu);
    __syncthreads();
    for (int i = tid; i < TT * 16; i += 256) {
        int t = i >> 4, c = (i & 15) * 4;
        float4 v = *reinterpret_cast<const float4*>(
            E + (size_t)sidx[t] * DIM + d0 + c);
        s[t][c] = v.x; s[t][c + 1] = v.y; s[t][c + 2] = v.z; s[t][c + 3] = v.w;
    }
    __syncthreads();
    for (int i = tid; i < 64 * TT; i += 256) {
        int dd = i / TT, t = i % TT;
        out[((size_t)b * DIM + d0 + dd) * TT + t] = s[t][dd];
    }
}

// loss accumulation: one warp per token row (exact fp32)
__global__ void k_loss(const float* __restrict__ E) {
    __shared__ float wsum[8];
    int warp = threadIdx.x >> 5, lane = threadIdx.x & 31;
    int n = blockIdx.x * 8 + warp;
    int idx = (int)(g_best[n] & 0xFFFFFFFFu);
    const float4* e4 = reinterpret_cast<const float4*>(E + (size_t)idx * DIM);
    const float4* x4 = reinterpret_cast<const float4*>(g_xT + (size_t)n * DIM);
    float s = 0.f;
#pragma unroll
    for (int i = 0; i < 4; i++) {
        float4 a = e4[lane + i * 32], b = x4[lane + i * 32];
        float dx = a.x - b.x, dy = a.y - b.y, dz = a.z - b.z, dw = a.w - b.w;
        s += dx * dx + dy * dy + dz * dz + dw * dw;
    }
#pragma unroll
    for (int o = 16; o; o >>= 1) s += __shfl_xor_sync(~0u, s, o);
    if (lane == 0) wsum[warp] = s;
    __syncthreads();
    if (threadIdx.x == 0) {
        float t = 0.f;
#pragma unroll
        for (int i = 0; i < 8; i++) t += wsum[i];
        atomicAdd(&g_loss_acc, (double)t);
    }
}

__global__ void k_finalize(float* out, int out_size) {
    if (out_size > NELEM)
        out[NELEM] = (float)(1.25 * g_loss_acc / (double)((size_t)NTOK * DIM));
}

// ---------------------------------------------------------------------------
extern "C" void kernel_launch(void* const* d_in, const int* in_sizes, int n_in,
                              void* d_out, int out_size) {
    const float* x = (const float*)d_in[0];
    const float* E = (const float*)d_in[1];
    float* out = (float*)d_out;

    k_init<<<(NTOK + 255) / 256, 256>>>();
    k_prep_x<<<dim3(TT / 32, DIM / 32, BATCH), dim3(32, 8)>>>(x);
    k_prep_e<<<(KEMB * DIM) / 256, 256>>>(E);
    k_esq<<<KEMB / 8, 256>>>(E);
    k_gemm_hmma<<<dim3(KEMB / BN, NTOK / BM), 256>>>();
    k_select<<<(NTOK + 255) / 256, 256>>>();
    k_fallback<<<512, 256>>>(E);
    k_output<<<dim3(DIM / 64, BATCH), 256>>>(E, out);
    k_loss<<<NTOK / 8, 256>>>(E);
    k_finalize<<<1, 1>>>(out, out_size);
}

// round 5
// speedup vs baseline: 4.4486x; 1.1618x over previous
#include <cuda_runtime.h>
#include <cuda_fp16.h>
#include <cstdint>

// Problem constants
#define BATCH 256
#define DIM   512
#define TT    96
#define NTOK  (BATCH * TT)        // 24576
#define KEMB  8192
#define NELEM (BATCH * DIM * TT)  // 12582912

// GEMM tiling (K = DIM = 512, fp16 hi only)
#define BM 128
#define BN 128
#define BK 32
#define NKIT (DIM / BK)           // 16
#define LDS_PAD 40                // halfs per smem row (32 + 8 pad)
#define NSTG 3
#define A_BYTES (BM * LDS_PAD * 2)        // 10240
#define STG_BYTES (2 * A_BYTES)           // 20480 (A then B)
#define DYN_SMEM (NSTG * STG_BYTES)       // 61440

#define MARGIN_F 0.4f

// Scratch (static device allocations are allowed)
__device__ __half g_Ah[(size_t)NTOK * DIM];    // 25 MB fp16 hi tokens
__device__ __half g_Bh[(size_t)KEMB * DIM];    // 8.4 MB fp16 hi embeddings
__device__ float  g_xT[(size_t)NTOK * DIM];    // 48 MB fp32 tokens (fallback)
__device__ float  g_esq[KEMB];
__device__ unsigned long long g_best[NTOK];    // packed (mapped_score<<32)|idx
__device__ unsigned int g_best2[NTOK];         // mapped second-best score
__device__ int g_nfall;
__device__ int g_fall[NTOK];
__device__ double g_loss_acc;

// ---------------------------------------------------------------------------
__device__ __forceinline__ unsigned long long pack_score(float s, int idx) {
    unsigned u = __float_as_uint(s);
    u = (u & 0x80000000u) ? ~u : (u | 0x80000000u);  // order-preserving map
    return ((unsigned long long)u << 32) | (unsigned)idx;
}
__device__ __forceinline__ float unmap_score(unsigned u) {
    unsigned v = (u & 0x80000000u) ? (u & 0x7FFFFFFFu) : ~u;
    return __uint_as_float(v);
}
__device__ __forceinline__ void cp_async16(uint32_t smem, const void* gmem) {
    asm volatile("cp.async.cg.shared.global [%0], [%1], 16;\n" ::"r"(smem), "l"(gmem));
}
__device__ __forceinline__ void upd2(unsigned long long& b1, unsigned& b2,
                                     unsigned long long c) {
    if (c < b1) { unsigned d = (unsigned)(b1 >> 32); if (d < b2) b2 = d; b1 = c; }
    else        { unsigned d = (unsigned)(c  >> 32); if (d < b2) b2 = d; }
}

// ---------------------------------------------------------------------------
__global__ void k_init() {
    int i = blockIdx.x * blockDim.x + threadIdx.x;
    if (i < NTOK) { g_best[i] = 0xFFFFFFFFFFFFFFFFULL; g_best2[i] = 0xFFFFFFFFu; }
    if (i == 0) { g_loss_acc = 0.0; g_nfall = 0; }
}

// x [B, D, T] -> g_xT fp32 [(b*T+t), d] AND g_Ah fp16 hi
__global__ void k_prep_x(const float* __restrict__ x) {
    __shared__ float tile[32][33];
    int b  = blockIdx.z;
    int d0 = blockIdx.y * 32;
    int t0 = blockIdx.x * 32;
    int tx = threadIdx.x, ty = threadIdx.y;
#pragma unroll
    for (int j = 0; j < 4; j++) {
        int d = d0 + ty + j * 8;
        tile[ty + j * 8][tx] = x[((size_t)b * DIM + d) * TT + t0 + tx];
    }
    __syncthreads();
#pragma unroll
    for (int j = 0; j < 4; j++) {
        int t = t0 + ty + j * 8;
        size_t row = (size_t)b * TT + t;
        float v = tile[tx][ty + j * 8];
        g_xT[row * DIM + d0 + tx] = v;
        g_Ah[row * DIM + d0 + tx] = __float2half(v);
    }
}

// Fused: E [K, D] -> g_Bh fp16 hi AND g_esq = ||e||^2. One warp per row.
__global__ void k_prep_e(const float* __restrict__ E) {
    int warp = (blockIdx.x * blockDim.x + threadIdx.x) >> 5;
    int lane = threadIdx.x & 31;
    if (warp >= KEMB) return;
    const float4* row = reinterpret_cast<const float4*>(E + (size_t)warp * DIM);
    __half2* dst = reinterpret_cast<__half2*>(g_Bh + (size_t)warp * DIM);
    float s = 0.f;
#pragma unroll
    for (int i = 0; i < 4; i++) {
        float4 v = row[lane + i * 32];
        s += v.x * v.x + v.y * v.y + v.z * v.z + v.w * v.w;
        dst[(lane + i * 32) * 2]     = __floats2half2_rn(v.x, v.y);
        dst[(lane + i * 32) * 2 + 1] = __floats2half2_rn(v.z, v.w);
    }
#pragma unroll
    for (int o = 16; o; o >>= 1) s += __shfl_xor_sync(~0u, s, o);
    if (lane == 0) g_esq[warp] = s;
}

// ---------------------------------------------------------------------------
// fp16-hi distance GEMM + fused per-row (min1, min2) tracking via HMMA.
// CTA = 128 rows x 128 embeddings, K = 512. 8 warps, warp tile 64x32.
// 3-stage cp.async pipeline, 2 CTAs/SM.
__global__ __launch_bounds__(256, 2) void k_gemm_hmma() {
    extern __shared__ char dyn[];
    __shared__ unsigned long long sb1[BM];
    __shared__ unsigned int sb2[BM];
    __shared__ float s_esq[BN];

    const int tid  = threadIdx.x;
    const int lane = tid & 31;
    const int wid  = tid >> 5;
    const int warprow = wid >> 2;      // 0..1 -> m offset 0/64
    const int warpcol = wid & 3;       // 0..3 -> n offset 0/32/64/96
    const int row0 = blockIdx.y * BM;
    const int n0   = blockIdx.x * BN;
    const uint32_t dbase = (uint32_t)__cvta_generic_to_shared(dyn);

    for (int i = tid; i < BM; i += 256) {
        sb1[i] = 0xFFFFFFFFFFFFFFFFULL;
        sb2[i] = 0xFFFFFFFFu;
    }
    if (tid < BN) s_esq[tid] = g_esq[n0 + tid];

    // loader mapping: 256 threads; A: 512 segs of 16B; B same.
    const int ldrow = tid >> 1;
    const int ldseg = (tid & 1) * 2;                 // seg pair {0,1} or {2,3}
    const __half* gA = g_Ah + (size_t)(row0 + ldrow) * DIM + ldseg * 8;
    const __half* gB = g_Bh + (size_t)(n0 + ldrow) * DIM + ldseg * 8;
    const uint32_t sAoff = (uint32_t)(ldrow * LDS_PAD + ldseg * 8) * 2;

    auto load_stage = [&](int kt, int stg) {
        const __half* a = gA + (size_t)kt * BK;
        const __half* b = gB + (size_t)kt * BK;
        uint32_t sa = dbase + stg * STG_BYTES + sAoff;
        uint32_t sb = sa + A_BYTES;
        cp_async16(sa, a);
        cp_async16(sa + 16, a + 8);
        cp_async16(sb, b);
        cp_async16(sb + 16, b + 8);
    };

    float acc[16][4];
#pragma unroll
    for (int i = 0; i < 16; i++)
#pragma unroll
        for (int c = 0; c < 4; c++) acc[i][c] = 0.f;

    // ldmatrix per-lane source rows/cols
    const int a_r = lane & 15;
    const int a_c = (lane >> 4) << 3;
    // B x4: covers 16 n-rows x 16 k. lane groups of 8:
    const int b_g   = lane & 7;
    const int b_sel = lane >> 3;                     // 0..3
    const int b_roff = ((b_sel & 2) ? 8 : 0) + b_g;  // row within 16-n block
    const int b_coff = (b_sel & 1) ? 8 : 0;          // k offset

    load_stage(0, 0);
    asm volatile("cp.async.commit_group;\n");
    load_stage(1, 1);
    asm volatile("cp.async.commit_group;\n");

    for (int kt = 0; kt < NKIT; kt++) {
        __syncthreads();   // all threads done computing on stage (kt+2)%NSTG
        if (kt + 2 < NKIT) {
            load_stage(kt + 2, (kt + 2) % NSTG);
            asm volatile("cp.async.commit_group;\n");
            asm volatile("cp.async.wait_group %0;\n" ::"n"(2));
        } else {
            asm volatile("cp.async.wait_group %0;\n" ::"n"(0));
        }
        __syncthreads();

        const uint32_t sA = dbase + (kt % NSTG) * STG_BYTES;
        const uint32_t sB = sA + A_BYTES;

#pragma unroll
        for (int kk = 0; kk < 2; kk++) {
            int k0 = kk * 16;
            uint32_t a_reg[4][4];
            uint32_t b_reg[2][4];
#pragma unroll
            for (int mf = 0; mf < 4; mf++) {
                int m0 = warprow * 64 + mf * 16;
                uint32_t addr = sA +
                    (uint32_t)(((m0 + a_r) * LDS_PAD + k0 + a_c) * 2);
                asm volatile(
                    "ldmatrix.sync.aligned.m8n8.x4.shared.b16 {%0,%1,%2,%3}, [%4];\n"
                    : "=r"(a_reg[mf][0]), "=r"(a_reg[mf][1]),
                      "=r"(a_reg[mf][2]), "=r"(a_reg[mf][3])
                    : "r"(addr));
            }
#pragma unroll
            for (int nh = 0; nh < 2; nh++) {         // each x4 = two n8 tiles
                int nn = warpcol * 32 + nh * 16;
                uint32_t addr = sB +
                    (uint32_t)(((nn + b_roff) * LDS_PAD + k0 + b_coff) * 2);
                asm volatile(
                    "ldmatrix.sync.aligned.m8n8.x4.shared.b16 {%0,%1,%2,%3}, [%4];\n"
                    : "=r"(b_reg[nh][0]), "=r"(b_reg[nh][1]),
                      "=r"(b_reg[nh][2]), "=r"(b_reg[nh][3])
                    : "r"(addr));
            }
#pragma unroll
            for (int mf = 0; mf < 4; mf++)
#pragma unroll
                for (int nf = 0; nf < 4; nf++) {
                    const uint32_t* b2p = &b_reg[nf >> 1][(nf & 1) * 2];
                    asm volatile(
                        "mma.sync.aligned.m16n8k16.row.col.f32.f16.f16.f32 "
                        "{%0,%1,%2,%3}, {%4,%5,%6,%7}, {%8,%9}, {%0,%1,%2,%3};\n"
                        : "+f"(acc[mf * 4 + nf][0]), "+f"(acc[mf * 4 + nf][1]),
                          "+f"(acc[mf * 4 + nf][2]), "+f"(acc[mf * 4 + nf][3])
                        : "r"(a_reg[mf][0]), "r"(a_reg[mf][1]),
                          "r"(a_reg[mf][2]), "r"(a_reg[mf][3]),
                          "r"(b2p[0]), "r"(b2p[1]));
                }
        }
    }
    __syncthreads();

    // Epilogue: score = ||e||^2 - 2*dot ; track per-row min1 (packed) + min2.
#pragma unroll
    for (int mf = 0; mf < 4; mf++) {
        int r0 = warprow * 64 + mf * 16 + (lane >> 2);
        unsigned long long b1a = 0xFFFFFFFFFFFFFFFFULL, b1b = 0xFFFFFFFFFFFFFFFFULL;
        unsigned b2a = 0xFFFFFFFFu, b2b = 0xFFFFFFFFu;
#pragma unroll
        for (int nf = 0; nf < 4; nf++) {
            int kl = warpcol * 32 + nf * 8 + 2 * (lane & 3);
            int k = n0 + kl;
            float e0 = s_esq[kl], e1 = s_esq[kl + 1];
            upd2(b1a, b2a, pack_score(e0 - 2.f * acc[mf * 4 + nf][0], k));
            upd2(b1a, b2a, pack_score(e1 - 2.f * acc[mf * 4 + nf][1], k + 1));
            upd2(b1b, b2b, pack_score(e0 - 2.f * acc[mf * 4 + nf][2], k));
            upd2(b1b, b2b, pack_score(e1 - 2.f * acc[mf * 4 + nf][3], k + 1));
        }
#pragma unroll
        for (int o = 1; o < 4; o <<= 1) {
            unsigned long long o1a = __shfl_xor_sync(0xffffffffu, b1a, o);
            unsigned long long o1b = __shfl_xor_sync(0xffffffffu, b1b, o);
            unsigned o2a = __shfl_xor_sync(0xffffffffu, b2a, o);
            unsigned o2b = __shfl_xor_sync(0xffffffffu, b2b, o);
            unsigned long long mxa = (b1a > o1a) ? b1a : o1a;
            unsigned long long mxb = (b1b > o1b) ? b1b : o1b;
            b1a = (b1a < o1a) ? b1a : o1a;
            b1b = (b1b < o1b) ? b1b : o1b;
            b2a = min(min(b2a, o2a), (unsigned)(mxa >> 32));
            b2b = min(min(b2b, o2b), (unsigned)(mxb >> 32));
        }
        if ((lane & 3) == 0) {
            unsigned long long old, disp;
            old = atomicMin(&sb1[r0], b1a);
            disp = (old > b1a) ? old : b1a;
            atomicMin(&sb2[r0], min(b2a, (unsigned)(disp >> 32)));
            old = atomicMin(&sb1[r0 + 8], b1b);
            disp = (old > b1b) ? old : b1b;
            atomicMin(&sb2[r0 + 8], min(b2b, (unsigned)(disp >> 32)));
        }
    }
    __syncthreads();
    for (int i = tid; i < BM; i += 256) {
        unsigned long long v1 = sb1[i];
        unsigned long long old = atomicMin(&g_best[row0 + i], v1);
        unsigned long long disp = (old > v1) ? old : v1;
        atomicMin(&g_best2[row0 + i], min(sb2[i], (unsigned)(disp >> 32)));
    }
}

// ---------------------------------------------------------------------------
// Flag rows with uncertain winner (approx gap < MARGIN) for exact rescore.
__global__ void k_select() {
    int i = blockIdx.x * blockDim.x + threadIdx.x;
    if (i >= NTOK) return;
    float s1 = unmap_score((unsigned)(g_best[i] >> 32));
    float s2 = unmap_score(g_best2[i]);
    if (s2 - s1 < MARGIN_F) {
        int p = atomicAdd(&g_nfall, 1);
        g_fall[p] = i;
        g_best[i] = 0xFFFFFFFFFFFFFFFFULL;
    }
}

// Exact fp32 rescore of flagged rows over all K embeddings.
// Grid = 512 CTAs: 64 batch slots x 8 embedding chunks of 1024.
__global__ __launch_bounds__(256) void k_fallback(const float* __restrict__ E) {
    __shared__ float xs[16][512];
    __shared__ int srow[16];
    __shared__ unsigned long long sb[16];
    const int n = g_nfall;
    const int chunk = blockIdx.x & 7;
    const int slot  = blockIdx.x >> 3;
    const int tid = threadIdx.x;

    for (int b = slot; b * 16 < n; b += 64) {
        int nr = min(16, n - b * 16);
        if (tid < 16) {
            srow[tid] = (tid < nr) ? g_fall[b * 16 + tid] : 0;
            sb[tid] = 0xFFFFFFFFFFFFFFFFULL;
        }
        __syncthreads();
        for (int idx = tid; idx < 16 * 512; idx += 256) {
            int r = idx >> 9, j = idx & 511;
            xs[r][j] = (r < nr) ? g_xT[(size_t)srow[r] * DIM + j] : 0.f;
        }
        __syncthreads();

        float bscore[16];
        int bidx[16];
#pragma unroll
        for (int r = 0; r < 16; r++) { bscore[r] = __int_as_float(0x7f800000); bidx[r] = 0; }

#pragma unroll 1
        for (int e = 0; e < 4; e++) {
            int k = chunk * 1024 + e * 256 + tid;
            float acc[16];
#pragma unroll
            for (int r = 0; r < 16; r++) acc[r] = 0.f;
            const float4* e4 = reinterpret_cast<const float4*>(E + (size_t)k * DIM);
            for (int jj = 0; jj < 128; jj++) {
                float4 v = e4[jj];
#pragma unroll
                for (int r = 0; r < 16; r++) {
                    float4 xv = *reinterpret_cast<const float4*>(&xs[r][jj * 4]);
                    acc[r] += v.x * xv.x + v.y * xv.y + v.z * xv.z + v.w * xv.w;
                }
            }
            float ek = g_esq[k];
#pragma unroll
            for (int r = 0; r < 16; r++) {
                float sc = ek - 2.f * acc[r];
                if (sc < bscore[r]) { bscore[r] = sc; bidx[r] = k; }
            }
        }
#pragma unroll
        for (int r = 0; r < 16; r++)
            if (r < nr) atomicMin(&sb[r], pack_score(bscore[r], bidx[r]));
        __syncthreads();
        if (tid < nr) atomicMin(&g_best[srow[tid]], sb[tid]);
        __syncthreads();
    }
}

// ---------------------------------------------------------------------------
// Gather quantized = E[idx], permute back to [B, D, T], and fused loss accum.
__global__ void k_output(const float* __restrict__ E, const float* __restrict__ x,
                         float* __restrict__ out) {
    __shared__ float s[TT][68];
    __shared__ int sidx[TT];
    __shared__ float wred[8];
    int b  = blockIdx.y;
    int d0 = blockIdx.x * 64;
    int tid = threadIdx.x;
    if (tid < TT) sidx[tid] = (int)(g_best[(size_t)b * TT + tid] & 0xFFFFFFFFu);
    __syncthreads();
    for (int i = tid; i < TT * 16; i += 256) {
        int t = i >> 4, c = (i & 15) * 4;
        float4 v = *reinterpret_cast<const float4*>(
            E + (size_t)sidx[t] * DIM + d0 + c);
        s[t][c] = v.x; s[t][c + 1] = v.y; s[t][c + 2] = v.z; s[t][c + 3] = v.w;
    }
    __syncthreads();
    float fsum = 0.f;
    for (int i = tid; i < 64 * TT; i += 256) {
        int dd = i / TT, t = i % TT;
        float e = s[t][dd];
        size_t off = ((size_t)b * DIM + d0 + dd) * TT + t;
        float df = e - x[off];
        fsum += df * df;
        out[off] = e;
    }
#pragma unroll
    for (int o = 16; o; o >>= 1) fsum += __shfl_xor_sync(~0u, fsum, o);
    if ((tid & 31) == 0) wred[tid >> 5] = fsum;
    __syncthreads();
    if (tid == 0) {
        float t = 0.f;
#pragma unroll
        for (int i = 0; i < 8; i++) t += wred[i];
        atomicAdd(&g_loss_acc, (double)t);
    }
}

__global__ void k_finalize(float* out, int out_size) {
    if (out_size > NELEM)
        out[NELEM] = (float)(1.25 * g_loss_acc / (double)((size_t)NTOK * DIM));
}

// ---------------------------------------------------------------------------
extern "C" void kernel_launch(void* const* d_in, const int* in_sizes, int n_in,
                              void* d_out, int out_size) {
    const float* x = (const float*)d_in[0];
    const float* E = (const float*)d_in[1];
    float* out = (float*)d_out;

    static int configured = 0;
    if (!configured) {
        cudaFuncSetAttribute(k_gemm_hmma,
                             cudaFuncAttributeMaxDynamicSharedMemorySize, DYN_SMEM);
        configured = 1;
    }

    k_init<<<(NTOK + 255) / 256, 256>>>();
    k_prep_x<<<dim3(TT / 32, DIM / 32, BATCH), dim3(32, 8)>>>(x);
    k_prep_e<<<KEMB / 8, 256>>>(E);
    k_gemm_hmma<<<dim3(KEMB / BN, NTOK / BM), 256, DYN_SMEM>>>();
    k_select<<<(NTOK + 255) / 256, 256>>>();
    k_fallback<<<512, 256>>>(E);
    k_output<<<dim3(DIM / 64, BATCH), 256>>>(E, x, out);
    k_finalize<<<1, 1>>>(out, out_size);
}

// round 6
// speedup vs baseline: 4.5287x; 1.0180x over previous
#include <cuda_runtime.h>
#include <cuda_fp16.h>
#include <cstdint>

// Problem constants
#define BATCH 256
#define DIM   512
#define TT    96
#define NTOK  (BATCH * TT)        // 24576
#define KEMB  8192
#define NELEM (BATCH * DIM * TT)  // 12582912

// GEMM tiling (K = DIM = 512, fp16 hi only)
#define BM 128
#define BN 256
#define BK 32
#define NKIT (DIM / BK)           // 16
#define LDS_PAD 40                // halfs per smem row (32 + 8 pad) -> 80 B pitch
#define NSTG 3
#define STG_ROWS (BM + BN)                 // 384
#define STG_BYTES (STG_ROWS * LDS_PAD * 2) // 30720
#define DYN_SMEM (NSTG * STG_BYTES)        // 92160

#define MARGIN_F 0.15f
#define FB_CHUNKS 16

// Scratch (static device allocations are allowed)
__device__ __half g_Ah[(size_t)NTOK * DIM];    // 25 MB fp16 hi tokens
__device__ __half g_Bh[(size_t)KEMB * DIM];    // 8.4 MB fp16 hi embeddings
__device__ float  g_xT[(size_t)NTOK * DIM];    // 48 MB fp32 tokens (fallback)
__device__ float  g_esq[KEMB];
__device__ unsigned long long g_best[NTOK];    // packed (mapped_score<<32)|idx
__device__ unsigned int g_best2[NTOK];         // mapped second-best score
__device__ int g_nfall;
__device__ int g_fall[NTOK];
__device__ double g_loss_acc;

// ---------------------------------------------------------------------------
__device__ __forceinline__ unsigned long long pack_score(float s, int idx) {
    unsigned u = __float_as_uint(s);
    u = (u & 0x80000000u) ? ~u : (u | 0x80000000u);  // order-preserving map
    return ((unsigned long long)u << 32) | (unsigned)idx;
}
__device__ __forceinline__ float unmap_score(unsigned u) {
    unsigned v = (u & 0x80000000u) ? (u & 0x7FFFFFFFu) : ~u;
    return __uint_as_float(v);
}
__device__ __forceinline__ void cp_async16(uint32_t smem, const void* gmem) {
    asm volatile("cp.async.cg.shared.global [%0], [%1], 16;\n" ::"r"(smem), "l"(gmem));
}
__device__ __forceinline__ void upd2(unsigned long long& b1, unsigned& b2,
                                     unsigned long long c) {
    if (c < b1) { unsigned d = (unsigned)(b1 >> 32); if (d < b2) b2 = d; b1 = c; }
    else        { unsigned d = (unsigned)(c  >> 32); if (d < b2) b2 = d; }
}

// ---------------------------------------------------------------------------
__global__ void k_init() {
    int i = blockIdx.x * blockDim.x + threadIdx.x;
    if (i < NTOK) { g_best[i] = 0xFFFFFFFFFFFFFFFFULL; g_best2[i] = 0xFFFFFFFFu; }
    if (i == 0) { g_loss_acc = 0.0; g_nfall = 0; }
}

// x [B, D, T] -> g_xT fp32 [(b*T+t), d] AND g_Ah fp16 hi
__global__ void k_prep_x(const float* __restrict__ x) {
    __shared__ float tile[32][33];
    int b  = blockIdx.z;
    int d0 = blockIdx.y * 32;
    int t0 = blockIdx.x * 32;
    int tx = threadIdx.x, ty = threadIdx.y;
#pragma unroll
    for (int j = 0; j < 4; j++) {
        int d = d0 + ty + j * 8;
        tile[ty + j * 8][tx] = x[((size_t)b * DIM + d) * TT + t0 + tx];
    }
    __syncthreads();
#pragma unroll
    for (int j = 0; j < 4; j++) {
        int t = t0 + ty + j * 8;
        size_t row = (size_t)b * TT + t;
        float v = tile[tx][ty + j * 8];
        g_xT[row * DIM + d0 + tx] = v;
        g_Ah[row * DIM + d0 + tx] = __float2half(v);
    }
}

// Fused: E [K, D] -> g_Bh fp16 hi AND g_esq = ||e||^2. One warp per row.
__global__ void k_prep_e(const float* __restrict__ E) {
    int warp = (blockIdx.x * blockDim.x + threadIdx.x) >> 5;
    int lane = threadIdx.x & 31;
    if (warp >= KEMB) return;
    const float4* row = reinterpret_cast<const float4*>(E + (size_t)warp * DIM);
    __half2* dst = reinterpret_cast<__half2*>(g_Bh + (size_t)warp * DIM);
    float s = 0.f;
#pragma unroll
    for (int i = 0; i < 4; i++) {
        float4 v = row[lane + i * 32];
        s += v.x * v.x + v.y * v.y + v.z * v.z + v.w * v.w;
        dst[(lane + i * 32) * 2]     = __floats2half2_rn(v.x, v.y);
        dst[(lane + i * 32) * 2 + 1] = __floats2half2_rn(v.z, v.w);
    }
#pragma unroll
    for (int o = 16; o; o >>= 1) s += __shfl_xor_sync(~0u, s, o);
    if (lane == 0) g_esq[warp] = s;
}

// ---------------------------------------------------------------------------
// fp16-hi distance GEMM + fused per-row (min1, min2) tracking via HMMA.
// CTA = 128 rows x 256 embeddings. 8 warps, warp tile 64x64. 3-stage cp.async.
__global__ __launch_bounds__(256, 1) void k_gemm_hmma() {
    extern __shared__ char dyn[];
    __shared__ unsigned long long sb1[BM];
    __shared__ unsigned int sb2[BM];
    __shared__ float s_esq[BN];

    const int tid  = threadIdx.x;
    const int lane = tid & 31;
    const int wid  = tid >> 5;
    const int warprow = wid >> 2;      // 0..1 -> m offset 0/64
    const int warpcol = wid & 3;       // 0..3 -> n offset 0/64/128/192
    const int row0 = blockIdx.y * BM;
    const int n0   = blockIdx.x * BN;
    const uint32_t dbase = (uint32_t)__cvta_generic_to_shared(dyn);

    for (int i = tid; i < BM; i += 256) {
        sb1[i] = 0xFFFFFFFFFFFFFFFFULL;
        sb2[i] = 0xFFFFFFFFu;
    }
    s_esq[tid] = g_esq[n0 + tid];      // BN == 256 == blockDim

    // loader: 384 rows x 64 B (4 segs of 16B). thread -> 6 (row, seg) pairs:
    // row = tid>>2 + 64*i, seg = tid&3.
    const int rbase = tid >> 2;
    const int seg   = tid & 3;
    const __half* gsrc[6];
    uint32_t soff[6];
#pragma unroll
    for (int i = 0; i < 6; i++) {
        int r = rbase + 64 * i;
        gsrc[i] = (r < BM ? g_Ah + (size_t)(row0 + r) * DIM
                          : g_Bh + (size_t)(n0 + r - BM) * DIM) + seg * 8;
        soff[i] = (uint32_t)(r * (LDS_PAD * 2) + seg * 16);
    }

    auto load_stage = [&](int kt, int stg) {
        uint32_t sbase = dbase + stg * STG_BYTES;
#pragma unroll
        for (int i = 0; i < 6; i++)
            cp_async16(sbase + soff[i], gsrc[i] + kt * BK);
    };

    float acc[4][8][4];
#pragma unroll
    for (int mf = 0; mf < 4; mf++)
#pragma unroll
        for (int nf = 0; nf < 8; nf++)
#pragma unroll
            for (int c = 0; c < 4; c++) acc[mf][nf][c] = 0.f;

    // ldmatrix per-lane rows/cols
    const int a_r = lane & 15;
    const int a_c = (lane >> 4) << 3;
    const int b_g   = lane & 7;
    const int b_sel = lane >> 3;
    const int b_roff = ((b_sel & 2) ? 8 : 0) + b_g;
    const int b_coff = (b_sel & 1) ? 8 : 0;

    load_stage(0, 0);
    asm volatile("cp.async.commit_group;\n");
    load_stage(1, 1);
    asm volatile("cp.async.commit_group;\n");

    for (int kt = 0; kt < NKIT; kt++) {
        __syncthreads();
        if (kt + 2 < NKIT) {
            load_stage(kt + 2, (kt + 2) % NSTG);
            asm volatile("cp.async.commit_group;\n");
            asm volatile("cp.async.wait_group %0;\n" ::"n"(2));
        } else {
            asm volatile("cp.async.wait_group %0;\n" ::"n"(0));
        }
        __syncthreads();

        const uint32_t sS = dbase + (kt % NSTG) * STG_BYTES;

#pragma unroll
        for (int kk = 0; kk < 2; kk++) {
            int k0 = kk * 16;
            uint32_t a_reg[4][4];
            uint32_t b_reg[4][4];
#pragma unroll
            for (int mf = 0; mf < 4; mf++) {
                int m0 = warprow * 64 + mf * 16;
                uint32_t addr = sS +
                    (uint32_t)(((m0 + a_r) * LDS_PAD + k0 + a_c) * 2);
                asm volatile(
                    "ldmatrix.sync.aligned.m8n8.x4.shared.b16 {%0,%1,%2,%3}, [%4];\n"
                    : "=r"(a_reg[mf][0]), "=r"(a_reg[mf][1]),
                      "=r"(a_reg[mf][2]), "=r"(a_reg[mf][3])
                    : "r"(addr));
            }
#pragma unroll
            for (int nh = 0; nh < 4; nh++) {         // each x4 = two n8 tiles
                int nn = warpcol * 64 + nh * 16;
                uint32_t addr = sS +
                    (uint32_t)(((BM + nn + b_roff) * LDS_PAD + k0 + b_coff) * 2);
                asm volatile(
                    "ldmatrix.sync.aligned.m8n8.x4.shared.b16 {%0,%1,%2,%3}, [%4];\n"
                    : "=r"(b_reg[nh][0]), "=r"(b_reg[nh][1]),
                      "=r"(b_reg[nh][2]), "=r"(b_reg[nh][3])
                    : "r"(addr));
            }
#pragma unroll
            for (int mf = 0; mf < 4; mf++)
#pragma unroll
                for (int nf = 0; nf < 8; nf++) {
                    const uint32_t* b2p = &b_reg[nf >> 1][(nf & 1) * 2];
                    asm volatile(
                        "mma.sync.aligned.m16n8k16.row.col.f32.f16.f16.f32 "
                        "{%0,%1,%2,%3}, {%4,%5,%6,%7}, {%8,%9}, {%0,%1,%2,%3};\n"
                        : "+f"(acc[mf][nf][0]), "+f"(acc[mf][nf][1]),
                          "+f"(acc[mf][nf][2]), "+f"(acc[mf][nf][3])
                        : "r"(a_reg[mf][0]), "r"(a_reg[mf][1]),
                          "r"(a_reg[mf][2]), "r"(a_reg[mf][3]),
                          "r"(b2p[0]), "r"(b2p[1]));
                }
        }
    }
    __syncthreads();

    // Epilogue: score = ||e||^2 - 2*dot ; per-row min1 (packed) + min2 (mapped).
#pragma unroll
    for (int mf = 0; mf < 4; mf++) {
        int r0 = warprow * 64 + mf * 16 + (lane >> 2);
        unsigned long long b1a = 0xFFFFFFFFFFFFFFFFULL, b1b = 0xFFFFFFFFFFFFFFFFULL;
        unsigned b2a = 0xFFFFFFFFu, b2b = 0xFFFFFFFFu;
#pragma unroll
        for (int nf = 0; nf < 8; nf++) {
            int kl = warpcol * 64 + nf * 8 + 2 * (lane & 3);
            int k = n0 + kl;
            float e0 = s_esq[kl], e1 = s_esq[kl + 1];
            upd2(b1a, b2a, pack_score(e0 - 2.f * acc[mf][nf][0], k));
            upd2(b1a, b2a, pack_score(e1 - 2.f * acc[mf][nf][1], k + 1));
            upd2(b1b, b2b, pack_score(e0 - 2.f * acc[mf][nf][2], k));
            upd2(b1b, b2b, pack_score(e1 - 2.f * acc[mf][nf][3], k + 1));
        }
#pragma unroll
        for (int o = 1; o < 4; o <<= 1) {
            unsigned long long o1a = __shfl_xor_sync(0xffffffffu, b1a, o);
            unsigned long long o1b = __shfl_xor_sync(0xffffffffu, b1b, o);
            unsigned o2a = __shfl_xor_sync(0xffffffffu, b2a, o);
            unsigned o2b = __shfl_xor_sync(0xffffffffu, b2b, o);
            unsigned long long mxa = (b1a > o1a) ? b1a : o1a;
            unsigned long long mxb = (b1b > o1b) ? b1b : o1b;
            b1a = (b1a < o1a) ? b1a : o1a;
            b1b = (b1b < o1b) ? b1b : o1b;
            b2a = min(min(b2a, o2a), (unsigned)(mxa >> 32));
            b2b = min(min(b2b, o2b), (unsigned)(mxb >> 32));
        }
        if ((lane & 3) == 0) {
            unsigned long long old, disp;
            old = atomicMin(&sb1[r0], b1a);
            disp = (old > b1a) ? old : b1a;
            atomicMin(&sb2[r0], min(b2a, (unsigned)(disp >> 32)));
            old = atomicMin(&sb1[r0 + 8], b1b);
            disp = (old > b1b) ? old : b1b;
            atomicMin(&sb2[r0 + 8], min(b2b, (unsigned)(disp >> 32)));
        }
    }
    __syncthreads();
    for (int i = tid; i < BM; i += 256) {
        unsigned long long v1 = sb1[i];
        unsigned long long old = atomicMin(&g_best[row0 + i], v1);
        unsigned long long disp = (old > v1) ? old : v1;
        atomicMin(&g_best2[row0 + i], min(sb2[i], (unsigned)(disp >> 32)));
    }
}

// ---------------------------------------------------------------------------
// Flag rows with uncertain winner (approx gap < MARGIN) for exact rescore.
__global__ void k_select() {
    int i = blockIdx.x * blockDim.x + threadIdx.x;
    if (i >= NTOK) return;
    float s1 = unmap_score((unsigned)(g_best[i] >> 32));
    float s2 = unmap_score(g_best2[i]);
    if (s2 - s1 < MARGIN_F) {
        int p = atomicAdd(&g_nfall, 1);
        g_fall[p] = i;
        g_best[i] = 0xFFFFFFFFFFFFFFFFULL;
    }
}

// Exact fp32 rescore of flagged rows over all K embeddings.
// Grid = 1024 CTAs: 64 batch slots x 16 embedding chunks of 512.
__global__ __launch_bounds__(256) void k_fallback(const float* __restrict__ E) {
    __shared__ float xs[16][512];
    __shared__ int srow[16];
    __shared__ unsigned long long sb[16];
    const int n = g_nfall;
    const int chunk = blockIdx.x & (FB_CHUNKS - 1);
    const int slot  = blockIdx.x / FB_CHUNKS;
    const int tid = threadIdx.x;

    for (int b = slot; b * 16 < n; b += 64) {
        int nr = min(16, n - b * 16);
        if (tid < 16) {
            srow[tid] = (tid < nr) ? g_fall[b * 16 + tid] : 0;
            sb[tid] = 0xFFFFFFFFFFFFFFFFULL;
        }
        __syncthreads();
        for (int idx = tid; idx < 16 * 512; idx += 256) {
            int r = idx >> 9, j = idx & 511;
            xs[r][j] = (r < nr) ? g_xT[(size_t)srow[r] * DIM + j] : 0.f;
        }
        __syncthreads();

        float bscore[16];
        int bidx[16];
#pragma unroll
        for (int r = 0; r < 16; r++) { bscore[r] = __int_as_float(0x7f800000); bidx[r] = 0; }

#pragma unroll 1
        for (int e = 0; e < 2; e++) {
            int k = chunk * (KEMB / FB_CHUNKS) + e * 256 + tid;
            float acc[16];
#pragma unroll
            for (int r = 0; r < 16; r++) acc[r] = 0.f;
            const float4* e4 = reinterpret_cast<const float4*>(E + (size_t)k * DIM);
            for (int jj = 0; jj < 128; jj++) {
                float4 v = e4[jj];
#pragma unroll
                for (int r = 0; r < 16; r++) {
                    float4 xv = *reinterpret_cast<const float4*>(&xs[r][jj * 4]);
                    acc[r] += v.x * xv.x + v.y * xv.y + v.z * xv.z + v.w * xv.w;
                }
            }
            float ek = g_esq[k];
#pragma unroll
            for (int r = 0; r < 16; r++) {
                float sc = ek - 2.f * acc[r];
                if (sc < bscore[r]) { bscore[r] = sc; bidx[r] = k; }
            }
        }
#pragma unroll
        for (int r = 0; r < 16; r++)
            if (r < nr) atomicMin(&sb[r], pack_score(bscore[r], bidx[r]));
        __syncthreads();
        if (tid < nr) atomicMin(&g_best[srow[tid]], sb[tid]);
        __syncthreads();
    }
}

// ---------------------------------------------------------------------------
// Gather quantized = E[idx], permute back to [B, D, T], and fused loss accum.
__global__ void k_output(const float* __restrict__ E, const float* __restrict__ x,
                         float* __restrict__ out) {
    __shared__ float s[TT][68];
    __shared__ int sidx[TT];
    __shared__ float wred[8];
    int b  = blockIdx.y;
    int d0 = blockIdx.x * 64;
    int tid = threadIdx.x;
    if (tid < TT) sidx[tid] = (int)(g_best[(size_t)b * TT + tid] & 0xFFFFFFFFu);
    __syncthreads();
    for (int i = tid; i < TT * 16; i += 256) {
        int t = i >> 4, c = (i & 15) * 4;
        float4 v = *reinterpret_cast<const float4*>(
            E + (size_t)sidx[t] * DIM + d0 + c);
        s[t][c] = v.x; s[t][c + 1] = v.y; s[t][c + 2] = v.z; s[t][c + 3] = v.w;
    }
    __syncthreads();
    float fsum = 0.f;
    for (int i = tid; i < 64 * TT; i += 256) {
        int dd = i / TT, t = i % TT;
        float e = s[t][dd];
        size_t off = ((size_t)b * DIM + d0 + dd) * TT + t;
        float df = e - x[off];
        fsum += df * df;
        out[off] = e;
    }
#pragma unroll
    for (int o = 16; o; o >>= 1) fsum += __shfl_xor_sync(~0u, fsum, o);
    if ((tid & 31) == 0) wred[tid >> 5] = fsum;
    __syncthreads();
    if (tid == 0) {
        float t = 0.f;
#pragma unroll
        for (int i = 0; i < 8; i++) t += wred[i];
        atomicAdd(&g_loss_acc, (double)t);
    }
}

__global__ void k_finalize(float* out, int out_size) {
    if (out_size > NELEM)
        out[NELEM] = (float)(1.25 * g_loss_acc / (double)((size_t)NTOK * DIM));
}

// ---------------------------------------------------------------------------
extern "C" void kernel_launch(void* const* d_in, const int* in_sizes, int n_in,
                              void* d_out, int out_size) {
    const float* x = (const float*)d_in[0];
    const float* E = (const float*)d_in[1];
    float* out = (float*)d_out;

    static int configured = 0;
    if (!configured) {
        cudaFuncSetAttribute(k_gemm_hmma,
                             cudaFuncAttributeMaxDynamicSharedMemorySize, DYN_SMEM);
        configured = 1;
    }

    k_init<<<(NTOK + 255) / 256, 256>>>();
    k_prep_x<<<dim3(TT / 32, DIM / 32, BATCH), dim3(32, 8)>>>(x);
    k_prep_e<<<KEMB / 8, 256>>>(E);
    k_gemm_hmma<<<dim3(KEMB / BN, NTOK / BM), 256, DYN_SMEM>>>();
    k_select<<<(NTOK + 255) / 256, 256>>>();
    k_fallback<<<64 * FB_CHUNKS, 256>>>(E);
    k_output<<<dim3(DIM / 64, BATCH), 256>>>(E, x, out);
    k_finalize<<<1, 1>>>(out, out_size);
}

// round 7
// speedup vs baseline: 5.6655x; 1.2510x over previous
#include <cuda_runtime.h>
#include <cuda_fp16.h>
#include <cstdint>

// Problem constants
#define BATCH 256
#define DIM   512
#define TT    96
#define NTOK  (BATCH * TT)        // 24576
#define KEMB  8192
#define NELEM (BATCH * DIM * TT)  // 12582912

// GEMM tiling (K = DIM = 512, fp16 hi only)
#define BM 128
#define BN 128
#define BK 32
#define NKIT (DIM / BK)           // 16
#define LDS_PAD 40                // halfs per smem row (32 + 8 pad) -> 80 B pitch
#define NSTG 4
#define A_BYTES (BM * LDS_PAD * 2)        // 10240
#define STG_BYTES (2 * A_BYTES)           // 20480 (A then B)
#define DYN_SMEM (NSTG * STG_BYTES)       // 81920

#define MARGIN_F 0.15f
#define FB_CHUNKS 16

// Scratch (static device allocations are allowed)
__device__ __half g_Ah[(size_t)NTOK * DIM];    // 25 MB fp16 hi tokens
__device__ __half g_Bh[(size_t)KEMB * DIM];    // 8.4 MB fp16 hi embeddings
__device__ float  g_xT[(size_t)NTOK * DIM];    // 48 MB fp32 tokens (fallback)
__device__ float  g_esq[KEMB];
__device__ unsigned long long g_best[NTOK];    // packed (mapped_score<<32)|idx
__device__ unsigned int g_best2[NTOK];         // mapped second-best score
__device__ int g_nfall;
__device__ int g_fall[NTOK];
__device__ double g_loss_acc;

// ---------------------------------------------------------------------------
__device__ __forceinline__ unsigned long long pack_score(float s, int idx) {
    unsigned u = __float_as_uint(s);
    u = (u & 0x80000000u) ? ~u : (u | 0x80000000u);  // order-preserving map
    return ((unsigned long long)u << 32) | (unsigned)idx;
}
__device__ __forceinline__ float unmap_score(unsigned u) {
    unsigned v = (u & 0x80000000u) ? (u & 0x7FFFFFFFu) : ~u;
    return __uint_as_float(v);
}
__device__ __forceinline__ void cp_async16(uint32_t smem, const void* gmem) {
    asm volatile("cp.async.cg.shared.global [%0], [%1], 16;\n" ::"r"(smem), "l"(gmem));
}
__device__ __forceinline__ void upd2(unsigned long long& b1, unsigned& b2,
                                     unsigned long long c) {
    if (c < b1) { unsigned d = (unsigned)(b1 >> 32); if (d < b2) b2 = d; b1 = c; }
    else        { unsigned d = (unsigned)(c  >> 32); if (d < b2) b2 = d; }
}

// ---------------------------------------------------------------------------
__global__ void k_init() {
    int i = blockIdx.x * blockDim.x + threadIdx.x;
    if (i < NTOK) { g_best[i] = 0xFFFFFFFFFFFFFFFFULL; g_best2[i] = 0xFFFFFFFFu; }
    if (i == 0) { g_loss_acc = 0.0; g_nfall = 0; }
}

// x [B, D, T] -> g_xT fp32 [(b*T+t), d] AND g_Ah fp16 hi
__global__ void k_prep_x(const float* __restrict__ x) {
    __shared__ float tile[32][33];
    int b  = blockIdx.z;
    int d0 = blockIdx.y * 32;
    int t0 = blockIdx.x * 32;
    int tx = threadIdx.x, ty = threadIdx.y;
#pragma unroll
    for (int j = 0; j < 4; j++) {
        int d = d0 + ty + j * 8;
        tile[ty + j * 8][tx] = x[((size_t)b * DIM + d) * TT + t0 + tx];
    }
    __syncthreads();
#pragma unroll
    for (int j = 0; j < 4; j++) {
        int t = t0 + ty + j * 8;
        size_t row = (size_t)b * TT + t;
        float v = tile[tx][ty + j * 8];
        g_xT[row * DIM + d0 + tx] = v;
        g_Ah[row * DIM + d0 + tx] = __float2half(v);
    }
}

// Fused: E [K, D] -> g_Bh fp16 hi AND g_esq = ||e||^2. One warp per row.
__global__ void k_prep_e(const float* __restrict__ E) {
    int warp = (blockIdx.x * blockDim.x + threadIdx.x) >> 5;
    int lane = threadIdx.x & 31;
    if (warp >= KEMB) return;
    const float4* row = reinterpret_cast<const float4*>(E + (size_t)warp * DIM);
    __half2* dst = reinterpret_cast<__half2*>(g_Bh + (size_t)warp * DIM);
    float s = 0.f;
#pragma unroll
    for (int i = 0; i < 4; i++) {
        float4 v = row[lane + i * 32];
        s += v.x * v.x + v.y * v.y + v.z * v.z + v.w * v.w;
        dst[(lane + i * 32) * 2]     = __floats2half2_rn(v.x, v.y);
        dst[(lane + i * 32) * 2 + 1] = __floats2half2_rn(v.z, v.w);
    }
#pragma unroll
    for (int o = 16; o; o >>= 1) s += __shfl_xor_sync(~0u, s, o);
    if (lane == 0) g_esq[warp] = s;
}

// ---------------------------------------------------------------------------
// fp16-hi distance GEMM + fused per-row (min1, min2) tracking via HMMA.
// CTA = 128 rows x 128 embeddings, K = 512. 8 warps, warp tile 64x32.
// 4-stage cp.async pipeline, ONE barrier per k-iteration, 2 CTAs/SM.
__global__ __launch_bounds__(256, 2) void k_gemm_hmma() {
    extern __shared__ char dyn[];
    __shared__ unsigned long long sb1[BM];
    __shared__ unsigned int sb2[BM];
    __shared__ float s_esq[BN];

    const int tid  = threadIdx.x;
    const int lane = tid & 31;
    const int wid  = tid >> 5;
    const int warprow = wid >> 2;      // 0..1 -> m offset 0/64
    const int warpcol = wid & 3;       // 0..3 -> n offset 0/32/64/96
    const int row0 = blockIdx.y * BM;
    const int n0   = blockIdx.x * BN;
    const uint32_t dbase = (uint32_t)__cvta_generic_to_shared(dyn);

    for (int i = tid; i < BM; i += 256) {
        sb1[i] = 0xFFFFFFFFFFFFFFFFULL;
        sb2[i] = 0xFFFFFFFFu;
    }
    if (tid < BN) s_esq[tid] = g_esq[n0 + tid];

    // loader mapping: 256 threads; A: 512 segs of 16B; B same.
    const int ldrow = tid >> 1;
    const int ldseg = (tid & 1) * 2;                 // seg pair {0,1} or {2,3}
    const __half* gA = g_Ah + (size_t)(row0 + ldrow) * DIM + ldseg * 8;
    const __half* gB = g_Bh + (size_t)(n0 + ldrow) * DIM + ldseg * 8;
    const uint32_t sAoff = (uint32_t)(ldrow * LDS_PAD + ldseg * 8) * 2;

    auto load_stage = [&](int kt, int stg) {
        const __half* a = gA + (size_t)kt * BK;
        const __half* b = gB + (size_t)kt * BK;
        uint32_t sa = dbase + stg * STG_BYTES + sAoff;
        uint32_t sb = sa + A_BYTES;
        cp_async16(sa, a);
        cp_async16(sa + 16, a + 8);
        cp_async16(sb, b);
        cp_async16(sb + 16, b + 8);
    };

    float acc[16][4];
#pragma unroll
    for (int i = 0; i < 16; i++)
#pragma unroll
        for (int c = 0; c < 4; c++) acc[i][c] = 0.f;

    // ldmatrix per-lane source rows/cols
    const int a_r = lane & 15;
    const int a_c = (lane >> 4) << 3;
    // B x4: covers 16 n-rows x 16 k. lane groups of 8:
    const int b_g   = lane & 7;
    const int b_sel = lane >> 3;                     // 0..3
    const int b_roff = ((b_sel & 2) ? 8 : 0) + b_g;  // row within 16-n block
    const int b_coff = (b_sel & 1) ? 8 : 0;          // k offset

    // prologue: 3 stages in flight
    load_stage(0, 0);
    asm volatile("cp.async.commit_group;\n");
    load_stage(1, 1);
    asm volatile("cp.async.commit_group;\n");
    load_stage(2, 2);
    asm volatile("cp.async.commit_group;\n");

#pragma unroll
    for (int kt = 0; kt < NKIT; kt++) {
        // stage kt arrived (for this thread): leave pending groups capped.
        if (kt < NKIT - 2) {
            asm volatile("cp.async.wait_group %0;\n" ::"n"(2));
        } else if (kt == NKIT - 2) {
            asm volatile("cp.async.wait_group %0;\n" ::"n"(1));
        } else {
            asm volatile("cp.async.wait_group %0;\n" ::"n"(0));
        }
        // Single barrier: (a) publishes everyone's arrived stage-kt data,
        // (b) proves all warps finished compute kt-1, so stage (kt+3)%4
        //     (last read at kt-1) is safe to overwrite below.
        __syncthreads();
        if (kt + 3 < NKIT) {
            load_stage(kt + 3, (kt + 3) & 3);
            asm volatile("cp.async.commit_group;\n");
        }

        const uint32_t sA = dbase + (kt & 3) * STG_BYTES;
        const uint32_t sB = sA + A_BYTES;

#pragma unroll
        for (int kk = 0; kk < 2; kk++) {
            int k0 = kk * 16;
            uint32_t a_reg[4][4];
            uint32_t b_reg[2][4];
#pragma unroll
            for (int mf = 0; mf < 4; mf++) {
                int m0 = warprow * 64 + mf * 16;
                uint32_t addr = sA +
                    (uint32_t)(((m0 + a_r) * LDS_PAD + k0 + a_c) * 2);
                asm volatile(
                    "ldmatrix.sync.aligned.m8n8.x4.shared.b16 {%0,%1,%2,%3}, [%4];\n"
                    : "=r"(a_reg[mf][0]), "=r"(a_reg[mf][1]),
                      "=r"(a_reg[mf][2]), "=r"(a_reg[mf][3])
                    : "r"(addr));
            }
#pragma unroll
            for (int nh = 0; nh < 2; nh++) {         // each x4 = two n8 tiles
                int nn = warpcol * 32 + nh * 16;
                uint32_t addr = sB +
                    (uint32_t)(((nn + b_roff) * LDS_PAD + k0 + b_coff) * 2);
                asm volatile(
                    "ldmatrix.sync.aligned.m8n8.x4.shared.b16 {%0,%1,%2,%3}, [%4];\n"
                    : "=r"(b_reg[nh][0]), "=r"(b_reg[nh][1]),
                      "=r"(b_reg[nh][2]), "=r"(b_reg[nh][3])
                    : "r"(addr));
            }
#pragma unroll
            for (int mf = 0; mf < 4; mf++)
#pragma unroll
                for (int nf = 0; nf < 4; nf++) {
                    const uint32_t* b2p = &b_reg[nf >> 1][(nf & 1) * 2];
                    asm volatile(
                        "mma.sync.aligned.m16n8k16.row.col.f32.f16.f16.f32 "
                        "{%0,%1,%2,%3}, {%4,%5,%6,%7}, {%8,%9}, {%0,%1,%2,%3};\n"
                        : "+f"(acc[mf * 4 + nf][0]), "+f"(acc[mf * 4 + nf][1]),
                          "+f"(acc[mf * 4 + nf][2]), "+f"(acc[mf * 4 + nf][3])
                        : "r"(a_reg[mf][0]), "r"(a_reg[mf][1]),
                          "r"(a_reg[mf][2]), "r"(a_reg[mf][3]),
                          "r"(b2p[0]), "r"(b2p[1]));
                }
        }
    }
    __syncthreads();

    // Epilogue: score = ||e||^2 - 2*dot ; track per-row min1 (packed) + min2.
#pragma unroll
    for (int mf = 0; mf < 4; mf++) {
        int r0 = warprow * 64 + mf * 16 + (lane >> 2);
        unsigned long long b1a = 0xFFFFFFFFFFFFFFFFULL, b1b = 0xFFFFFFFFFFFFFFFFULL;
        unsigned b2a = 0xFFFFFFFFu, b2b = 0xFFFFFFFFu;
#pragma unroll
        for (int nf = 0; nf < 4; nf++) {
            int kl = warpcol * 32 + nf * 8 + 2 * (lane & 3);
            int k = n0 + kl;
            float e0 = s_esq[kl], e1 = s_esq[kl + 1];
            upd2(b1a, b2a, pack_score(e0 - 2.f * acc[mf * 4 + nf][0], k));
            upd2(b1a, b2a, pack_score(e1 - 2.f * acc[mf * 4 + nf][1], k + 1));
            upd2(b1b, b2b, pack_score(e0 - 2.f * acc[mf * 4 + nf][2], k));
            upd2(b1b, b2b, pack_score(e1 - 2.f * acc[mf * 4 + nf][3], k + 1));
        }
#pragma unroll
        for (int o = 1; o < 4; o <<= 1) {
            unsigned long long o1a = __shfl_xor_sync(0xffffffffu, b1a, o);
            unsigned long long o1b = __shfl_xor_sync(0xffffffffu, b1b, o);
            unsigned o2a = __shfl_xor_sync(0xffffffffu, b2a, o);
            unsigned o2b = __shfl_xor_sync(0xffffffffu, b2b, o);
            unsigned long long mxa = (b1a > o1a) ? b1a : o1a;
            unsigned long long mxb = (b1b > o1b) ? b1b : o1b;
            b1a = (b1a < o1a) ? b1a : o1a;
            b1b = (b1b < o1b) ? b1b : o1b;
            b2a = min(min(b2a, o2a), (unsigned)(mxa >> 32));
            b2b = min(min(b2b, o2b), (unsigned)(mxb >> 32));
        }
        if ((lane & 3) == 0) {
            unsigned long long old, disp;
            old = atomicMin(&sb1[r0], b1a);
            disp = (old > b1a) ? old : b1a;
            atomicMin(&sb2[r0], min(b2a, (unsigned)(disp >> 32)));
            old = atomicMin(&sb1[r0 + 8], b1b);
            disp = (old > b1b) ? old : b1b;
            atomicMin(&sb2[r0 + 8], min(b2b, (unsigned)(disp >> 32)));
        }
    }
    __syncthreads();
    for (int i = tid; i < BM; i += 256) {
        unsigned long long v1 = sb1[i];
        unsigned long long old = atomicMin(&g_best[row0 + i], v1);
        unsigned long long disp = (old > v1) ? old : v1;
        atomicMin(&g_best2[row0 + i], min(sb2[i], (unsigned)(disp >> 32)));
    }
}

// ---------------------------------------------------------------------------
// Flag rows with uncertain winner (approx gap < MARGIN) for exact rescore.
__global__ void k_select() {
    int i = blockIdx.x * blockDim.x + threadIdx.x;
    if (i >= NTOK) return;
    float s1 = unmap_score((unsigned)(g_best[i] >> 32));
    float s2 = unmap_score(g_best2[i]);
    if (s2 - s1 < MARGIN_F) {
        int p = atomicAdd(&g_nfall, 1);
        g_fall[p] = i;
        g_best[i] = 0xFFFFFFFFFFFFFFFFULL;
    }
}

// Exact fp32 rescore of flagged rows over all K embeddings.
// Grid = 1024 CTAs: 64 batch slots x 16 embedding chunks of 512.
__global__ __launch_bounds__(256) void k_fallback(const float* __restrict__ E) {
    __shared__ float xs[16][512];
    __shared__ int srow[16];
    __shared__ unsigned long long sb[16];
    const int n = g_nfall;
    const int chunk = blockIdx.x & (FB_CHUNKS - 1);
    const int slot  = blockIdx.x / FB_CHUNKS;
    const int tid = threadIdx.x;

    for (int b = slot; b * 16 < n; b += 64) {
        int nr = min(16, n - b * 16);
        if (tid < 16) {
            srow[tid] = (tid < nr) ? g_fall[b * 16 + tid] : 0;
            sb[tid] = 0xFFFFFFFFFFFFFFFFULL;
        }
        __syncthreads();
        for (int idx = tid; idx < 16 * 512; idx += 256) {
            int r = idx >> 9, j = idx & 511;
            xs[r][j] = (r < nr) ? g_xT[(size_t)srow[r] * DIM + j] : 0.f;
        }
        __syncthreads();

        float bscore[16];
        int bidx[16];
#pragma unroll
        for (int r = 0; r < 16; r++) { bscore[r] = __int_as_float(0x7f800000); bidx[r] = 0; }

#pragma unroll 1
        for (int e = 0; e < 2; e++) {
            int k = chunk * (KEMB / FB_CHUNKS) + e * 256 + tid;
            float acc[16];
#pragma unroll
            for (int r = 0; r < 16; r++) acc[r] = 0.f;
            const float4* e4 = reinterpret_cast<const float4*>(E + (size_t)k * DIM);
            for (int jj = 0; jj < 128; jj++) {
                float4 v = e4[jj];
#pragma unroll
                for (int r = 0; r < 16; r++) {
                    float4 xv = *reinterpret_cast<const float4*>(&xs[r][jj * 4]);
                    acc[r] += v.x * xv.x + v.y * xv.y + v.z * xv.z + v.w * xv.w;
                }
            }
            float ek = g_esq[k];
#pragma unroll
            for (int r = 0; r < 16; r++) {
                float sc = ek - 2.f * acc[r];
                if (sc < bscore[r]) { bscore[r] = sc; bidx[r] = k; }
            }
        }
#pragma unroll
        for (int r = 0; r < 16; r++)
            if (r < nr) atomicMin(&sb[r], pack_score(bscore[r], bidx[r]));
        __syncthreads();
        if (tid < nr) atomicMin(&g_best[srow[tid]], sb[tid]);
        __syncthreads();
    }
}

// ---------------------------------------------------------------------------
// Gather quantized = E[idx], permute back to [B, D, T], and fused loss accum.
__global__ void k_output(const float* __restrict__ E, const float* __restrict__ x,
                         float* __restrict__ out) {
    __shared__ float s[TT][68];
    __shared__ int sidx[TT];
    __shared__ float wred[8];
    int b  = blockIdx.y;
    int d0 = blockIdx.x * 64;
    int tid = threadIdx.x;
    if (tid < TT) sidx[tid] = (int)(g_best[(size_t)b * TT + tid] & 0xFFFFFFFFu);
    __syncthreads();
    for (int i = tid; i < TT * 16; i += 256) {
        int t = i >> 4, c = (i & 15) * 4;
        float4 v = *reinterpret_cast<const float4*>(
            E + (size_t)sidx[t] * DIM + d0 + c);
        s[t][c] = v.x; s[t][c + 1] = v.y; s[t][c + 2] = v.z; s[t][c + 3] = v.w;
    }
    __syncthreads();
    float fsum = 0.f;
    for (int i = tid; i < 64 * TT; i += 256) {
        int dd = i / TT, t = i % TT;
        float e = s[t][dd];
        size_t off = ((size_t)b * DIM + d0 + dd) * TT + t;
        float df = e - x[off];
        fsum += df * df;
        out[off] = e;
    }
#pragma unroll
    for (int o = 16; o; o >>= 1) fsum += __shfl_xor_sync(~0u, fsum, o);
    if ((tid & 31) == 0) wred[tid >> 5] = fsum;
    __syncthreads();
    if (tid == 0) {
        float t = 0.f;
#pragma unroll
        for (int i = 0; i < 8; i++) t += wred[i];
        atomicAdd(&g_loss_acc, (double)t);
    }
}

__global__ void k_finalize(float* out, int out_size) {
    if (out_size > NELEM)
        out[NELEM] = (float)(1.25 * g_loss_acc / (double)((size_t)NTOK * DIM));
}

// ---------------------------------------------------------------------------
extern "C" void kernel_launch(void* const* d_in, const int* in_sizes, int n_in,
                              void* d_out, int out_size) {
    const float* x = (const float*)d_in[0];
    const float* E = (const float*)d_in[1];
    float* out = (float*)d_out;

    static int configured = 0;
    if (!configured) {
        cudaFuncSetAttribute(k_gemm_hmma,
                             cudaFuncAttributeMaxDynamicSharedMemorySize, DYN_SMEM);
        configured = 1;
    }

    k_init<<<(NTOK + 255) / 256, 256>>>();
    k_prep_x<<<dim3(TT / 32, DIM / 32, BATCH), dim3(32, 8)>>>(x);
    k_prep_e<<<KEMB / 8, 256>>>(E);
    k_gemm_hmma<<<dim3(KEMB / BN, NTOK / BM), 256, DYN_SMEM>>>();
    k_select<<<(NTOK + 255) / 256, 256>>>();
    k_fallback<<<64 * FB_CHUNKS, 256>>>(E);
    k_output<<<dim3(DIM / 64, BATCH), 256>>>(E, x, out);
    k_finalize<<<1, 1>>>(out, out_size);
}

// round 8
// speedup vs baseline: 6.4231x; 1.1337x over previous
#include <cuda_runtime.h>
#include <cuda_fp16.h>
#include <cstdint>

// Problem constants
#define BATCH 256
#define DIM   512
#define TT    96
#define NTOK  (BATCH * TT)        // 24576
#define KEMB  8192
#define NELEM (BATCH * DIM * TT)  // 12582912

// GEMM tiling (K = DIM = 512, fp16 hi only)
#define BM 128
#define BN 128
#define BK 64
#define NKIT (DIM / BK)           // 8
#define PITCH 72                  // halfs per smem row (64 + 8 pad) -> 144 B
#define ROWB (PITCH * 2)          // 144
#define A_REGION (BM * ROWB)      // 18432
#define STG_BYTES ((BM + BN) * ROWB)  // 36864
#define NSTG 2
#define DYN_SMEM (NSTG * STG_BYTES)   // 73728

#define MARGIN_F 0.15f
#define FB_CHUNKS 16

// Scratch (static device allocations are allowed)
__device__ __half g_Ah[(size_t)NTOK * DIM];    // 25 MB fp16 hi tokens
__device__ __half g_Bh[(size_t)KEMB * DIM];    // 8.4 MB fp16 hi embeddings
__device__ float  g_esq[KEMB];
__device__ unsigned long long g_best[NTOK];    // packed (mapped_score<<32)|idx
__device__ unsigned int g_best2[NTOK];         // mapped second-best score
__device__ int g_nfall;
__device__ int g_fall[NTOK];
__device__ double g_loss_acc;

// ---------------------------------------------------------------------------
__device__ __forceinline__ unsigned long long pack_score(float s, int idx) {
    unsigned u = __float_as_uint(s);
    u = (u & 0x80000000u) ? ~u : (u | 0x80000000u);  // order-preserving map
    return ((unsigned long long)u << 32) | (unsigned)idx;
}
__device__ __forceinline__ float unmap_score(unsigned u) {
    unsigned v = (u & 0x80000000u) ? (u & 0x7FFFFFFFu) : ~u;
    return __uint_as_float(v);
}
__device__ __forceinline__ void cp_async16(uint32_t smem, const void* gmem) {
    asm volatile("cp.async.cg.shared.global [%0], [%1], 16;\n" ::"r"(smem), "l"(gmem));
}
__device__ __forceinline__ void upd2(unsigned long long& b1, unsigned& b2,
                                     unsigned long long c) {
    if (c < b1) { unsigned d = (unsigned)(b1 >> 32); if (d < b2) b2 = d; b1 = c; }
    else        { unsigned d = (unsigned)(c  >> 32); if (d < b2) b2 = d; }
}

// ---------------------------------------------------------------------------
__global__ void k_init() {
    int i = blockIdx.x * blockDim.x + threadIdx.x;
    if (i < NTOK) { g_best[i] = 0xFFFFFFFFFFFFFFFFULL; g_best2[i] = 0xFFFFFFFFu; }
    if (i == 0) { g_loss_acc = 0.0; g_nfall = 0; }
}

// x [B, D, T] -> g_Ah fp16 hi [(b*T+t), d]
__global__ void k_prep_x(const float* __restrict__ x) {
    __shared__ float tile[32][33];
    int b  = blockIdx.z;
    int d0 = blockIdx.y * 32;
    int t0 = blockIdx.x * 32;
    int tx = threadIdx.x, ty = threadIdx.y;
#pragma unroll
    for (int j = 0; j < 4; j++) {
        int d = d0 + ty + j * 8;
        tile[ty + j * 8][tx] = x[((size_t)b * DIM + d) * TT + t0 + tx];
    }
    __syncthreads();
#pragma unroll
    for (int j = 0; j < 4; j++) {
        int t = t0 + ty + j * 8;
        size_t row = (size_t)b * TT + t;
        g_Ah[row * DIM + d0 + tx] = __float2half(tile[tx][ty + j * 8]);
    }
}

// Fused: E [K, D] -> g_Bh fp16 hi AND g_esq = ||e||^2. One warp per row.
__global__ void k_prep_e(const float* __restrict__ E) {
    int warp = (blockIdx.x * blockDim.x + threadIdx.x) >> 5;
    int lane = threadIdx.x & 31;
    if (warp >= KEMB) return;
    const float4* row = reinterpret_cast<const float4*>(E + (size_t)warp * DIM);
    __half2* dst = reinterpret_cast<__half2*>(g_Bh + (size_t)warp * DIM);
    float s = 0.f;
#pragma unroll
    for (int i = 0; i < 4; i++) {
        float4 v = row[lane + i * 32];
        s += v.x * v.x + v.y * v.y + v.z * v.z + v.w * v.w;
        dst[(lane + i * 32) * 2]     = __floats2half2_rn(v.x, v.y);
        dst[(lane + i * 32) * 2 + 1] = __floats2half2_rn(v.z, v.w);
    }
#pragma unroll
    for (int o = 16; o; o >>= 1) s += __shfl_xor_sync(~0u, s, o);
    if (lane == 0) g_esq[warp] = s;
}

// ---------------------------------------------------------------------------
// fp16-hi distance GEMM + fused per-row (min1, min2) tracking via HMMA.
// CTA = 128 rows x 128 embeddings, K = 512. 8 warps, warp tile 64x32.
// BK=64 double buffer, ONE barrier per k-iteration (8 total), 2 CTAs/SM.
__global__ __launch_bounds__(256, 2) void k_gemm_hmma() {
    extern __shared__ char dyn[];
    __shared__ unsigned long long sb1[BM];
    __shared__ unsigned int sb2[BM];
    __shared__ float s_esq[BN];

    const int tid  = threadIdx.x;
    const int lane = tid & 31;
    const int wid  = tid >> 5;
    const int warprow = wid >> 2;      // 0..1 -> m offset 0/64
    const int warpcol = wid & 3;       // 0..3 -> n offset 0/32/64/96
    const int row0 = blockIdx.y * BM;
    const int n0   = blockIdx.x * BN;
    const uint32_t dbase = (uint32_t)__cvta_generic_to_shared(dyn);

    for (int i = tid; i < BM; i += 256) {
        sb1[i] = 0xFFFFFFFFFFFFFFFFULL;
        sb2[i] = 0xFFFFFFFFu;
    }
    if (tid < BN) s_esq[tid] = g_esq[n0 + tid];

    // loader: per stage 2048 16B segs (A 1024 + B 1024), 8 per thread.
    // g = i*256 + tid ; r = g>>3 (32i + rb), c = g&7. 128B contiguous per 8 thr.
    const int rb = tid >> 3;           // 0..31
    const int cs = tid & 7;            // seg in row
    const __half* gA = g_Ah + (size_t)(row0 + rb) * DIM + cs * 8;
    const __half* gB = g_Bh + (size_t)(n0 + rb) * DIM + cs * 8;
    const uint32_t sAoff = (uint32_t)(rb * ROWB + cs * 16);

    auto load_stage = [&](int kt, int stg) {
        uint32_t sa = dbase + stg * STG_BYTES + sAoff;
        const __half* a = gA + kt * BK;
        const __half* b = gB + kt * BK;
#pragma unroll
        for (int i = 0; i < 4; i++)
            cp_async16(sa + i * (32 * ROWB), a + (size_t)(32 * i) * DIM);
#pragma unroll
        for (int i = 0; i < 4; i++)
            cp_async16(sa + A_REGION + i * (32 * ROWB), b + (size_t)(32 * i) * DIM);
    };

    float acc[16][4];
#pragma unroll
    for (int i = 0; i < 16; i++)
#pragma unroll
        for (int c = 0; c < 4; c++) acc[i][c] = 0.f;

    // ldmatrix per-lane source rows/cols
    const int a_r = lane & 15;
    const int a_c = (lane >> 4) << 3;
    const int b_g   = lane & 7;
    const int b_sel = lane >> 3;                     // 0..3
    const int b_roff = ((b_sel & 2) ? 8 : 0) + b_g;  // row within 16-n block
    const int b_coff = (b_sel & 1) ? 8 : 0;          // k offset

    // per-warp ldmatrix byte offsets within a stage (stage-base added later)
    uint32_t a_off[4], b_off[2];
#pragma unroll
    for (int mf = 0; mf < 4; mf++)
        a_off[mf] = (uint32_t)((warprow * 64 + mf * 16 + a_r) * ROWB + a_c * 2);
#pragma unroll
    for (int nh = 0; nh < 2; nh++)
        b_off[nh] = (uint32_t)(A_REGION +
                    (warpcol * 32 + nh * 16 + b_roff) * ROWB + b_coff * 2);

    load_stage(0, 0);
    asm volatile("cp.async.commit_group;\n");

#pragma unroll
    for (int kt = 0; kt < NKIT; kt++) {
        asm volatile("cp.async.wait_group 0;\n");  // stage kt arrived (own copies)
        // Single barrier: publishes stage kt across threads AND proves all
        // warps finished compute kt-1, so slot (kt+1)&1 is free to overwrite.
        __syncthreads();
        if (kt + 1 < NKIT) {
            load_stage(kt + 1, (kt + 1) & 1);
            asm volatile("cp.async.commit_group;\n");
        }

        const uint32_t sS = dbase + (kt & 1) * STG_BYTES;

#pragma unroll
        for (int kk = 0; kk < 4; kk++) {           // four k16 steps per BK=64
            const uint32_t kb = kk * 32;           // 16 halfs = 32 B
            uint32_t a_reg[4][4];
            uint32_t b_reg[2][4];
#pragma unroll
            for (int mf = 0; mf < 4; mf++) {
                asm volatile(
                    "ldmatrix.sync.aligned.m8n8.x4.shared.b16 {%0,%1,%2,%3}, [%4];\n"
                    : "=r"(a_reg[mf][0]), "=r"(a_reg[mf][1]),
                      "=r"(a_reg[mf][2]), "=r"(a_reg[mf][3])
                    : "r"(sS + a_off[mf] + kb));
            }
#pragma unroll
            for (int nh = 0; nh < 2; nh++) {       // each x4 = two n8 tiles
                asm volatile(
                    "ldmatrix.sync.aligned.m8n8.x4.shared.b16 {%0,%1,%2,%3}, [%4];\n"
                    : "=r"(b_reg[nh][0]), "=r"(b_reg[nh][1]),
                      "=r"(b_reg[nh][2]), "=r"(b_reg[nh][3])
                    : "r"(sS + b_off[nh] + kb));
            }
#pragma unroll
            for (int mf = 0; mf < 4; mf++)
#pragma unroll
                for (int nf = 0; nf < 4; nf++) {
                    const uint32_t* b2p = &b_reg[nf >> 1][(nf & 1) * 2];
                    asm volatile(
                        "mma.sync.aligned.m16n8k16.row.col.f32.f16.f16.f32 "
                        "{%0,%1,%2,%3}, {%4,%5,%6,%7}, {%8,%9}, {%0,%1,%2,%3};\n"
                        : "+f"(acc[mf * 4 + nf][0]), "+f"(acc[mf * 4 + nf][1]),
                          "+f"(acc[mf * 4 + nf][2]), "+f"(acc[mf * 4 + nf][3])
                        : "r"(a_reg[mf][0]), "r"(a_reg[mf][1]),
                          "r"(a_reg[mf][2]), "r"(a_reg[mf][3]),
                          "r"(b2p[0]), "r"(b2p[1]));
                }
        }
    }
    __syncthreads();

    // Epilogue: score = ||e||^2 - 2*dot ; track per-row min1 (packed) + min2.
#pragma unroll
    for (int mf = 0; mf < 4; mf++) {
        int r0 = warprow * 64 + mf * 16 + (lane >> 2);
        unsigned long long b1a = 0xFFFFFFFFFFFFFFFFULL, b1b = 0xFFFFFFFFFFFFFFFFULL;
        unsigned b2a = 0xFFFFFFFFu, b2b = 0xFFFFFFFFu;
#pragma unroll
        for (int nf = 0; nf < 4; nf++) {
            int kl = warpcol * 32 + nf * 8 + 2 * (lane & 3);
            int k = n0 + kl;
            float e0 = s_esq[kl], e1 = s_esq[kl + 1];
            upd2(b1a, b2a, pack_score(e0 - 2.f * acc[mf * 4 + nf][0], k));
            upd2(b1a, b2a, pack_score(e1 - 2.f * acc[mf * 4 + nf][1], k + 1));
            upd2(b1b, b2b, pack_score(e0 - 2.f * acc[mf * 4 + nf][2], k));
            upd2(b1b, b2b, pack_score(e1 - 2.f * acc[mf * 4 + nf][3], k + 1));
        }
#pragma unroll
        for (int o = 1; o < 4; o <<= 1) {
            unsigned long long o1a = __shfl_xor_sync(0xffffffffu, b1a, o);
            unsigned long long o1b = __shfl_xor_sync(0xffffffffu, b1b, o);
            unsigned o2a = __shfl_xor_sync(0xffffffffu, b2a, o);
            unsigned o2b = __shfl_xor_sync(0xffffffffu, b2b, o);
            unsigned long long mxa = (b1a > o1a) ? b1a : o1a;
            unsigned long long mxb = (b1b > o1b) ? b1b : o1b;
            b1a = (b1a < o1a) ? b1a : o1a;
            b1b = (b1b < o1b) ? b1b : o1b;
            b2a = min(min(b2a, o2a), (unsigned)(mxa >> 32));
            b2b = min(min(b2b, o2b), (unsigned)(mxb >> 32));
        }
        if ((lane & 3) == 0) {
            unsigned long long old, disp;
            old = atomicMin(&sb1[r0], b1a);
            disp = (old > b1a) ? old : b1a;
            atomicMin(&sb2[r0], min(b2a, (unsigned)(disp >> 32)));
            old = atomicMin(&sb1[r0 + 8], b1b);
            disp = (old > b1b) ? old : b1b;
            atomicMin(&sb2[r0 + 8], min(b2b, (unsigned)(disp >> 32)));
        }
    }
    __syncthreads();
    for (int i = tid; i < BM; i += 256) {
        unsigned long long v1 = sb1[i];
        unsigned long long old = atomicMin(&g_best[row0 + i], v1);
        unsigned long long disp = (old > v1) ? old : v1;
        atomicMin(&g_best2[row0 + i], min(sb2[i], (unsigned)(disp >> 32)));
    }
}

// ---------------------------------------------------------------------------
// Flag rows with uncertain winner (approx gap < MARGIN) for exact rescore.
__global__ void k_select() {
    int i = blockIdx.x * blockDim.x + threadIdx.x;
    if (i >= NTOK) return;
    float s1 = unmap_score((unsigned)(g_best[i] >> 32));
    float s2 = unmap_score(g_best2[i]);
    if (s2 - s1 < MARGIN_F) {
        int p = atomicAdd(&g_nfall, 1);
        g_fall[p] = i;
        g_best[i] = 0xFFFFFFFFFFFFFFFFULL;
    }
}

// Exact fp32 rescore of flagged rows over all K embeddings.
// x rows are read straight from the original [B, D, T] layout (tiny volume).
// Grid = 1024 CTAs: 64 batch slots x 16 embedding chunks of 512.
__global__ __launch_bounds__(256) void k_fallback(const float* __restrict__ E,
                                                  const float* __restrict__ x) {
    __shared__ float xs[16][512];
    __shared__ int srow[16];
    __shared__ unsigned long long sb[16];
    const int n = g_nfall;
    const int chunk = blockIdx.x & (FB_CHUNKS - 1);
    const int slot  = blockIdx.x / FB_CHUNKS;
    const int tid = threadIdx.x;

    for (int b = slot; b * 16 < n; b += 64) {
        int nr = min(16, n - b * 16);
        if (tid < 16) {
            srow[tid] = (tid < nr) ? g_fall[b * 16 + tid] : 0;
            sb[tid] = 0xFFFFFFFFFFFFFFFFULL;
        }
        __syncthreads();
        for (int idx = tid; idx < 16 * 512; idx += 256) {
            int r = idx >> 9, j = idx & 511;
            int row = srow[r];
            xs[r][j] = (r < nr)
                ? x[((size_t)(row / TT) * DIM + j) * TT + (row % TT)] : 0.f;
        }
        __syncthreads();

        float bscore[16];
        int bidx[16];
#pragma unroll
        for (int r = 0; r < 16; r++) { bscore[r] = __int_as_float(0x7f800000); bidx[r] = 0; }

#pragma unroll 1
        for (int e = 0; e < 2; e++) {
            int k = chunk * (KEMB / FB_CHUNKS) + e * 256 + tid;
            float acc[16];
#pragma unroll
            for (int r = 0; r < 16; r++) acc[r] = 0.f;
            const float4* e4 = reinterpret_cast<const float4*>(E + (size_t)k * DIM);
            for (int jj = 0; jj < 128; jj++) {
                float4 v = e4[jj];
#pragma unroll
                for (int r = 0; r < 16; r++) {
                    float4 xv = *reinterpret_cast<const float4*>(&xs[r][jj * 4]);
                    acc[r] += v.x * xv.x + v.y * xv.y + v.z * xv.z + v.w * xv.w;
                }
            }
            float ek = g_esq[k];
#pragma unroll
            for (int r = 0; r < 16; r++) {
                float sc = ek - 2.f * acc[r];
                if (sc < bscore[r]) { bscore[r] = sc; bidx[r] = k; }
            }
        }
#pragma unroll
        for (int r = 0; r < 16; r++)
            if (r < nr) atomicMin(&sb[r], pack_score(bscore[r], bidx[r]));
        __syncthreads();
        if (tid < nr) atomicMin(&g_best[srow[tid]], sb[tid]);
        __syncthreads();
    }
}

// ---------------------------------------------------------------------------
// Gather quantized = E[idx], permute back to [B, D, T], and fused loss accum.
__global__ void k_output(const float* __restrict__ E, const float* __restrict__ x,
                         float* __restrict__ out) {
    __shared__ float s[TT][68];
    __shared__ int sidx[TT];
    __shared__ float wred[8];
    int b  = blockIdx.y;
    int d0 = blockIdx.x * 64;
    int tid = threadIdx.x;
    if (tid < TT) sidx[tid] = (int)(g_best[(size_t)b * TT + tid] & 0xFFFFFFFFu);
    __syncthreads();
    for (int i = tid; i < TT * 16; i += 256) {
        int t = i >> 4, c = (i & 15) * 4;
        float4 v = *reinterpret_cast<const float4*>(
            E + (size_t)sidx[t] * DIM + d0 + c);
        s[t][c] = v.x; s[t][c + 1] = v.y; s[t][c + 2] = v.z; s[t][c + 3] = v.w;
    }
    __syncthreads();
    float fsum = 0.f;
    for (int i = tid; i < 64 * TT; i += 256) {
        int dd = i / TT, t = i % TT;
        float e = s[t][dd];
        size_t off = ((size_t)b * DIM + d0 + dd) * TT + t;
        float df = e - x[off];
        fsum += df * df;
        out[off] = e;
    }
#pragma unroll
    for (int o = 16; o; o >>= 1) fsum += __shfl_xor_sync(~0u, fsum, o);
    if ((tid & 31) == 0) wred[tid >> 5] = fsum;
    __syncthreads();
    if (tid == 0) {
        float t = 0.f;
#pragma unroll
        for (int i = 0; i < 8; i++) t += wred[i];
        atomicAdd(&g_loss_acc, (double)t);
    }
}

__global__ void k_finalize(float* out, int out_size) {
    if (out_size > NELEM)
        out[NELEM] = (float)(1.25 * g_loss_acc / (double)((size_t)NTOK * DIM));
}

// ---------------------------------------------------------------------------
extern "C" void kernel_launch(void* const* d_in, const int* in_sizes, int n_in,
                              void* d_out, int out_size) {
    const float* x = (const float*)d_in[0];
    const float* E = (const float*)d_in[1];
    float* out = (float*)d_out;

    static int configured = 0;
    if (!configured) {
        cudaFuncSetAttribute(k_gemm_hmma,
                             cudaFuncAttributeMaxDynamicSharedMemorySize, DYN_SMEM);
        configured = 1;
    }

    k_init<<<(NTOK + 255) / 256, 256>>>();
    k_prep_x<<<dim3(TT / 32, DIM / 32, BATCH), dim3(32, 8)>>>(x);
    k_prep_e<<<KEMB / 8, 256>>>(E);
    k_gemm_hmma<<<dim3(KEMB / BN, NTOK / BM), 256, DYN_SMEM>>>();
    k_select<<<(NTOK + 255) / 256, 256>>>();
    k_fallback<<<64 * FB_CHUNKS, 256>>>(E, x);
    k_output<<<dim3(DIM / 64, BATCH), 256>>>(E, x, out);
    k_finalize<<<1, 1>>>(out, out_size);
}